// round 15
// baseline (speedup 1.0000x reference)
#include <cuda_runtime.h>
#include <cuda_bf16.h>
#include <cstdint>

#define BB 2
#define SS 2048
#define DD 768
#define HH 12
#define HDD 64
#define MROWS (BB*SS)   // 4096
#define NROWS_ATT (BB*HH*SS)   // 49152
#define SPLIT_QT 8      // split key range for qt >= SPLIT_QT

#if defined(__CUDA_ARCH__) && \
    ((__CUDA_ARCH__ == 1030 && defined(__CUDA_ARCH_FEAT_SM103_ALL)) || \
     (__CUDA_ARCH__ == 1000 && defined(__CUDA_ARCH_FEAT_SM100_ALL)) || \
     (__CUDA_ARCH__ == 1010 && defined(__CUDA_ARCH_FEAT_SM101_ALL)))
#define HAS_TC 1
#else
#define HAS_TC 0
#endif

// log2(e) folded into Q so softmax uses exp2
#define QSCALE 0.18033688011112042f   // 0.125 * log2(e)

// ---------------- device scratch (allocation-free rule) ----------------
__device__ __nv_bfloat16 g_xhi[MROWS*DD], g_xlo[MROWS*DD];
__device__ __nv_bfloat16 g_chi[MROWS*DD], g_clo[MROWS*DD];
__device__ __nv_bfloat16 g_wthi[4][DD*DD], g_wtlo[4][DD*DD];   // [N][K]
__device__ __nv_bfloat16 g_qhi[BB*HH*SS*HDD], g_qlo[BB*HH*SS*HDD];
__device__ __nv_bfloat16 g_khi[BB*HH*SS*HDD], g_klo[BB*HH*SS*HDD];
__device__ __nv_bfloat16 g_vthi[BB*HH*SS*HDD], g_vtlo[BB*HH*SS*HDD];
// split-K attention partials (only qt >= SPLIT_QT rows)
__device__ float g_po[2ull*NROWS_ATT*HDD];
__device__ float g_lp[2][NROWS_ATT];
__device__ int   g_flag[BB*HH*(16 - SPLIT_QT)];   // 192 finisher flags

// ---------------- PTX helpers ------------------------------------------
__device__ __forceinline__ uint32_t smem_u32(const void* p) {
    uint32_t a;
    asm("{ .reg .u64 t; cvta.to.shared.u64 t, %1; cvt.u32.u64 %0, t; }" : "=r"(a) : "l"(p));
    return a;
}
__device__ __forceinline__ float ex2_mufu(float x) {
    float r; asm("ex2.approx.f32 %0, %1;" : "=f"(r) : "f"(x)); return r;
}
// exp2 via FMA pipe: magic-constant floor + degree-4 poly on [-0.5, 0.5]
__device__ __forceinline__ float exp2_poly(float y) {
    y = fmaxf(y, -125.0f);
    float z = y + 12582912.0f;
    float f = y - (z - 12582912.0f);
    int   n = __float_as_int(z) - 0x4B400000;
    float p = 0.0096181291f;
    p = fmaf(p, f, 0.0555041087f);
    p = fmaf(p, f, 0.2402265069f);
    p = fmaf(p, f, 0.6931471806f);
    p = fmaf(p, f, 1.0f);
    return __int_as_float(__float_as_int(p) + (n << 23));
}

#if HAS_TC
__device__ __forceinline__ uint32_t elect_one_pred() {
    uint32_t pred;
    asm volatile(
        "{\n\t.reg .pred p;\n\telect.sync _|p, 0xFFFFFFFF;\n\tselp.b32 %0, 1, 0, p;\n\t}"
        : "=r"(pred));
    return pred;
}

#define TCGEN05_ALLOC(smem_result_addr, nCols) \
    asm volatile("tcgen05.alloc.cta_group::1.sync.aligned.shared::cta.b32 [%0], %1;" \
                 :: "r"((uint32_t)(smem_result_addr)), "r"((uint32_t)(nCols)) : "memory")
#define TCGEN05_DEALLOC(tmem_addr, nCols) \
    asm volatile("tcgen05.dealloc.cta_group::1.sync.aligned.b32 %0, %1;" \
                 :: "r"(tmem_addr), "r"((uint32_t)(nCols)))
#define TCGEN05_RELINQUISH() \
    asm volatile("tcgen05.relinquish_alloc_permit.cta_group::1.sync.aligned;")
#define TCGEN05_COMMIT(mbar) \
    asm volatile("tcgen05.commit.cta_group::1.mbarrier::arrive::one.shared::cluster.b64 [%0];" \
                 :: "r"((uint32_t)(mbar)) : "memory")
#define TCGEN05_WAIT_LD() asm volatile("tcgen05.wait::ld.sync.aligned;" ::: "memory")
#define TCGEN05_WAIT_ST() asm volatile("tcgen05.wait::st.sync.aligned;" ::: "memory")
#define TCGEN05_FENCE_AFTER() asm volatile("tcgen05.fence::after_thread_sync;" ::: "memory")
#define TCGEN05_FENCE_BEFORE() asm volatile("tcgen05.fence::before_thread_sync;" ::: "memory")
#define FENCE_PROXY_ASYNC() asm volatile("fence.proxy.async.shared::cta;" ::: "memory")

#define MBARRIER_INIT(mbar, count) \
    asm volatile("mbarrier.init.shared.b64 [%0], %1;" \
                 :: "r"((uint32_t)(mbar)), "r"((uint32_t)(count)) : "memory")
#define MBARRIER_INVAL(mbar) \
    asm volatile("mbarrier.inval.shared.b64 [%0];" :: "r"((uint32_t)(mbar)) : "memory")

#define MBARRIER_WAIT_PARITY(mbar_smem_addr, phase_parity) do { \
    uint32_t _mbar = (uint32_t)(mbar_smem_addr); \
    uint32_t _parity = (uint32_t)(phase_parity); \
    uint32_t _done; \
    asm volatile( \
        "{\n\t.reg .pred p;\n\t" \
        "mbarrier.try_wait.parity.acquire.cta.shared::cta.b64 p, [%1], %2;\n\t" \
        "selp.b32 %0, 1, 0, p;\n\t}" \
        : "=r"(_done) : "r"(_mbar), "r"(_parity) : "memory"); \
    if (!_done) { \
        asm volatile( \
            "{\n\t.reg .pred P1;\n\t" \
            "WAIT_LOOP_%=:\n\t" \
            "mbarrier.try_wait.parity.acquire.cta.shared::cta.b64 P1, [%0], %1, 0x989680;\n\t" \
            "@P1 bra.uni WAIT_DONE_%=;\n\t" \
            "bra.uni WAIT_LOOP_%=;\n\t" \
            "WAIT_DONE_%=:\n\t}" \
            :: "r"(_mbar), "r"(_parity) : "memory"); \
    } \
} while(0)

#define TCGEN05_LD_32X32B_X32(r, tmem_addr) \
    asm volatile( \
        "tcgen05.ld.sync.aligned.32x32b.x32.b32 " \
        "{%0, %1, %2, %3, %4, %5, %6, %7, " \
        " %8, %9, %10, %11, %12, %13, %14, %15, " \
        " %16, %17, %18, %19, %20, %21, %22, %23, " \
        " %24, %25, %26, %27, %28, %29, %30, %31}, [%32];" \
        : "=r"((r)[0]),  "=r"((r)[1]),  "=r"((r)[2]),  "=r"((r)[3]), \
          "=r"((r)[4]),  "=r"((r)[5]),  "=r"((r)[6]),  "=r"((r)[7]), \
          "=r"((r)[8]),  "=r"((r)[9]),  "=r"((r)[10]), "=r"((r)[11]), \
          "=r"((r)[12]), "=r"((r)[13]), "=r"((r)[14]), "=r"((r)[15]), \
          "=r"((r)[16]), "=r"((r)[17]), "=r"((r)[18]), "=r"((r)[19]), \
          "=r"((r)[20]), "=r"((r)[21]), "=r"((r)[22]), "=r"((r)[23]), \
          "=r"((r)[24]), "=r"((r)[25]), "=r"((r)[26]), "=r"((r)[27]), \
          "=r"((r)[28]), "=r"((r)[29]), "=r"((r)[30]), "=r"((r)[31]) \
        : "r"(tmem_addr))

#define TCGEN05_ST_32X32B_X16(tmem_addr, r) \
    asm volatile( \
        "tcgen05.st.sync.aligned.32x32b.x16.b32 [%0], " \
        "{%1, %2, %3, %4, %5, %6, %7, %8, " \
        " %9, %10, %11, %12, %13, %14, %15, %16};" \
        :: "r"(tmem_addr), \
           "r"((r)[0]),  "r"((r)[1]),  "r"((r)[2]),  "r"((r)[3]), \
           "r"((r)[4]),  "r"((r)[5]),  "r"((r)[6]),  "r"((r)[7]), \
           "r"((r)[8]),  "r"((r)[9]),  "r"((r)[10]), "r"((r)[11]), \
           "r"((r)[12]), "r"((r)[13]), "r"((r)[14]), "r"((r)[15]) \
        : "memory")

#define CP_ASYNC16(dst, src) \
    asm volatile("cp.async.cg.shared.global [%0], [%1], 16;" :: "r"(dst), "l"(src) : "memory")
#define CP_COMMIT() asm volatile("cp.async.commit_group;" ::: "memory")
#define CP_WAIT(n)  asm volatile("cp.async.wait_group %0;" :: "n"(n) : "memory")

__device__ __forceinline__ void mma_f16_ss(uint32_t d_tmem, uint64_t a_desc, uint64_t b_desc,
                                           uint32_t idesc, bool acc) {
    uint32_t en = acc ? 1u : 0u;
    uint32_t zero = 0u;
    asm volatile(
        "{\n\t.reg .pred p;\n\t"
        "setp.ne.u32 p, %5, 0;\n\t"
        "tcgen05.mma.cta_group::1.kind::f16 [%0], %1, %2, %3, {%4, %4, %4, %4}, p;\n\t}"
        :: "r"(d_tmem), "l"(a_desc), "l"(b_desc), "r"(idesc), "r"(zero), "r"(en)
        : "memory");
}

// TS form: A in TMEM
__device__ __forceinline__ void mma_f16_ts(uint32_t d_tmem, uint32_t a_tmem, uint64_t b_desc,
                                           uint32_t idesc, bool acc) {
    uint32_t en = acc ? 1u : 0u;
    uint32_t zero = 0u;
    asm volatile(
        "{\n\t.reg .pred p;\n\t"
        "setp.ne.u32 p, %5, 0;\n\t"
        "tcgen05.mma.cta_group::1.kind::f16 [%0], [%1], %2, %3, {%4, %4, %4, %4}, p;\n\t}"
        :: "r"(d_tmem), "r"(a_tmem), "l"(b_desc), "r"(idesc), "r"(zero), "r"(en)
        : "memory");
}
#endif  // HAS_TC

// SW128 (128B rows)
static constexpr uint64_t SMEM_DESC_BASE_SW128 =
    (uint64_t(2) << 61) | (uint64_t(1) << 46) | (uint64_t(64) << 32) | (uint64_t(1) << 16);
#define MAKE_SMEM_DESC(addr) (SMEM_DESC_BASE_SW128 | ((uint64_t)((addr) >> 4) & 0x3FFF))
#define SWZ128(off) ((off) ^ (((off) >> 3) & 0x70))

static constexpr uint32_t GEMM_IDESC =            // M=128, N=128
    (1u << 4) | (1u << 7) | (1u << 10) | (16u << 17) | (8u << 24);
static constexpr uint32_t ATT_IDESC =             // M=128, N=64
    (1u << 4) | (1u << 7) | (1u << 10) | (8u << 17) | (8u << 24);

__device__ __forceinline__ uint32_t pack_bf16x2(float a, float b) {
    __nv_bfloat162 t2 = __floats2bfloat162_rn(a, b);
    return *reinterpret_cast<uint32_t*>(&t2);
}

// -------- fused prep: weight transpose+split, x split, flag zero --------
__global__ void prep_kernel(const float* __restrict__ x,
                            const float* __restrict__ w0, const float* __restrict__ w1,
                            const float* __restrict__ w2, const float* __restrict__ w3)
{
    __shared__ float tile[32][33];
    const int bx = blockIdx.x;
    const int tid = threadIdx.x;
    if (bx == 0 && tid < BB*HH*(16 - SPLIT_QT)) g_flag[tid] = 0;

    if (bx < 2304) {
        const int widx = bx / 576;
        const int r = bx - widx * 576;
        const int n0 = (r % 24) * 32, k0 = (r / 24) * 32;
        const float* src = (widx == 0) ? w0 : (widx == 1) ? w1 : (widx == 2) ? w2 : w3;
        const int tx = tid & 31, ty = tid >> 5;   // (32, 8)
#pragma unroll
        for (int rr = 0; rr < 4; rr++)
            tile[ty + rr * 8][tx] = src[(k0 + ty + rr * 8) * DD + n0 + tx];
        __syncthreads();
        __nv_bfloat16* hiT = g_wthi[widx];
        __nv_bfloat16* loT = g_wtlo[widx];
#pragma unroll
        for (int rr = 0; rr < 4; rr++) {
            float v = tile[tx][ty + rr * 8];
            __nv_bfloat16 h = __float2bfloat16(v);
            int o = (n0 + ty + rr * 8) * DD + k0 + tx;
            hiT[o] = h;
            loT[o] = __float2bfloat16(v - __bfloat162float(h));
        }
    } else {
        const int i = (bx - 2304) * 256 + tid;
        float2 v = reinterpret_cast<const float2*>(x)[i];
        __nv_bfloat16 h0 = __float2bfloat16(v.x);
        __nv_bfloat16 h1 = __float2bfloat16(v.y);
        __nv_bfloat162 hp; hp.x = h0; hp.y = h1;
        __nv_bfloat162 lp;
        lp.x = __float2bfloat16(v.x - __bfloat162float(h0));
        lp.y = __float2bfloat16(v.y - __bfloat162float(h1));
        reinterpret_cast<__nv_bfloat162*>(g_xhi)[i] = hp;
        reinterpret_cast<__nv_bfloat162*>(g_xlo)[i] = lp;
    }
}

// ---------------- shared epilogue writer (Q/K/Y paths) ------------------
__device__ __forceinline__ void epi_store(int out_sel, int hh, int bb, int ss, int gRow,
                                          int cw, const float* vals,
                                          const float* __restrict__ bias, float* Y)
{
    if (out_sel == 3) {
        float* dst = Y + (size_t)gRow * DD + cw;
#pragma unroll
        for (int g = 0; g < 16; g++) {
            float4 o;
            o.x = vals[g*4+0] + __ldg(&bias[cw + g*4+0]);
            o.y = vals[g*4+1] + __ldg(&bias[cw + g*4+1]);
            o.z = vals[g*4+2] + __ldg(&bias[cw + g*4+2]);
            o.w = vals[g*4+3] + __ldg(&bias[cw + g*4+3]);
            *reinterpret_cast<float4*>(dst + g*4) = o;
        }
    } else if (out_sel <= 1) {
        __nv_bfloat16* Hi = out_sel ? g_khi : g_qhi;
        __nv_bfloat16* Lo = out_sel ? g_klo : g_qlo;
        const float sc = out_sel ? 1.0f : QSCALE;
        size_t ob = ((size_t)(bb * HH + hh) * SS + ss) * HDD;
#pragma unroll
        for (int g = 0; g < 8; g++) {
            uint32_t hw[4], lw[4];
#pragma unroll
            for (int e2 = 0; e2 < 4; e2++) {
                float v0 = (vals[g*8 + e2*2+0] + __ldg(&bias[cw + g*8 + e2*2+0])) * sc;
                float v1 = (vals[g*8 + e2*2+1] + __ldg(&bias[cw + g*8 + e2*2+1])) * sc;
                float h0 = __bfloat162float(__float2bfloat16(v0));
                float h1 = __bfloat162float(__float2bfloat16(v1));
                hw[e2] = pack_bf16x2(h0, h1);
                lw[e2] = pack_bf16x2(v0 - h0, v1 - h1);
            }
            *reinterpret_cast<uint4*>(Hi + ob + g*8) = *reinterpret_cast<uint4*>(hw);
            *reinterpret_cast<uint4*>(Lo + ob + g*8) = *reinterpret_cast<uint4*>(lw);
        }
    } else {
        size_t vb = (size_t)(bb * HH + hh) * HDD;
#pragma unroll
        for (int j = 0; j < 64; j++) {
            float v = vals[j] + __ldg(&bias[cw + j]);
            __nv_bfloat16 hb = __float2bfloat16(v);
            size_t o = (vb + j) * SS + ss;
            g_vthi[o] = hb;
            g_vtlo[o] = __float2bfloat16(v - __bfloat162float(hb));
        }
    }
}

// ---- GEMM: CTA 128x256, k-tile 64 (SW128), PIPELINED mainloop ----------
// MMA(kt) is issued BEFORE waiting on MMA(kt-1), so the tensor queue never
// drains; fill(kt+1) overlaps MMA(kt). Two mbarriers (one per buffer),
// strictly 1-outstanding each.
#define GB_AHI 0
#define GB_ALO 16384
#define GB_BHI 32768
#define GB_BLO 65536
#define GB_SIZE 98304
#define GM_TOTAL (1024 + 2*GB_SIZE)   // 197632

#if HAS_TC
__device__ __forceinline__ void gemm_fill(uint32_t buf,
                                          const __nv_bfloat16* __restrict__ Ahi,
                                          const __nv_bfloat16* __restrict__ Alo,
                                          const __nv_bfloat16* __restrict__ Bhi,
                                          const __nv_bfloat16* __restrict__ Blo,
                                          int rowBase, int k0, int t)
{
#pragma unroll
    for (int i = 0; i < 8; i++) {          // A: 128 rows x 64 k
        int idx = i * 128 + t;
        int r = idx >> 3, s = idx & 7;
        size_t g = (size_t)(rowBase + r) * DD + k0 + s * 8;
        uint32_t off = SWZ128((uint32_t)(r * 128 + s * 16));
        CP_ASYNC16(buf + GB_AHI + off, (const char*)(Ahi + g));
        CP_ASYNC16(buf + GB_ALO + off, (const char*)(Alo + g));
    }
#pragma unroll
    for (int i = 0; i < 16; i++) {         // B: 256 rows x 64 k
        int idx = i * 128 + t;
        int r = idx >> 3, s = idx & 7;
        size_t g = (size_t)r * DD + k0 + s * 8;
        uint32_t off = SWZ128((uint32_t)(r * 128 + s * 16));
        CP_ASYNC16(buf + GB_BHI + off, (const char*)(Bhi + g));
        CP_ASYNC16(buf + GB_BLO + off, (const char*)(Blo + g));
    }
}
#endif

__global__ __launch_bounds__(128) void tc_gemm(
    const float* __restrict__ b0, const float* __restrict__ b1, const float* __restrict__ b2,
    float* __restrict__ Y, int in_sel, int mode)  // mode 0 = fused QKV, 1 = O-proj
{
    extern __shared__ char smem[];
    const int t = threadIdx.x;
    const int cb = blockIdx.x;
    const int rowBase = blockIdx.y * 128;

    int w, rowInW;
    if (mode == 0) { w = cb / 3; rowInW = (cb - w * 3) * 256; }
    else           { w = 3;      rowInW = cb * 256; }

    const __nv_bfloat16* Ahi = in_sel ? g_chi : g_xhi;
    const __nv_bfloat16* Alo = in_sel ? g_clo : g_xlo;
    const __nv_bfloat16* Bhi = g_wthi[w] + (size_t)rowInW * DD;
    const __nv_bfloat16* Blo = g_wtlo[w] + (size_t)rowInW * DD;

    const int gRow = rowBase + t;
    const int bb = gRow >> 11, ss = gRow & 2047;

#if HAS_TC
    const uint32_t sbase = smem_u32(smem);
    const int wid = t >> 5;

    if (wid == 0) { TCGEN05_ALLOC(sbase, 256); TCGEN05_RELINQUISH(); }
    if (t == 0) { MBARRIER_INIT(sbase + 8, 1); MBARRIER_INIT(sbase + 16, 1); }
    __syncthreads();
    uint32_t tmem;
    asm volatile("ld.shared.b32 %0, [%1];" : "=r"(tmem) : "r"(sbase));

    const int nkt = DD / 64;   // 12
    gemm_fill(sbase + 1024, Ahi, Alo, Bhi, Blo, rowBase, 0, t);
    CP_COMMIT();

    for (int kt = 0; kt < nkt; kt++) {
        const uint32_t buf = sbase + 1024 + (kt & 1) * GB_SIZE;
        // fill(kt) complete + visible
        CP_WAIT(0);
        FENCE_PROXY_ASYNC();
        __syncthreads();

        // issue MMA(kt) FIRST (tensor queue stays fed while MMA(kt-1) runs)
        if (wid == 0) {
            if (elect_one_pred()) {
                const uint64_t dAhi = MAKE_SMEM_DESC(buf + GB_AHI);
                const uint64_t dAlo = MAKE_SMEM_DESC(buf + GB_ALO);
                const uint64_t dBhi = MAKE_SMEM_DESC(buf + GB_BHI);
                const uint64_t dBlo = MAKE_SMEM_DESC(buf + GB_BLO);
#pragma unroll
                for (int ks = 0; ks < 4; ks++) {
#pragma unroll
                    for (int nh = 0; nh < 2; nh++) {
                        const uint64_t ao = ks * 2;
                        const uint64_t bo = nh * 1024 + ks * 2;
                        const bool first = (kt == 0) && (ks == 0);
                        mma_f16_ss(tmem + nh * 128, dAhi + ao, dBhi + bo, GEMM_IDESC, !first);
                        mma_f16_ss(tmem + nh * 128, dAhi + ao, dBlo + bo, GEMM_IDESC, true);
                        mma_f16_ss(tmem + nh * 128, dAlo + ao, dBhi + bo, GEMM_IDESC, true);
                    }
                }
                TCGEN05_COMMIT(sbase + 8 + (kt & 1) * 8);
            }
        }

        // now free the other buffer (reader = MMA(kt-1)) and refill it
        if (kt + 1 < nkt) {
            if (kt > 0)
                MBARRIER_WAIT_PARITY(sbase + 8 + ((kt - 1) & 1) * 8, ((kt - 1) >> 1) & 1);
            gemm_fill(sbase + 1024 + ((kt + 1) & 1) * GB_SIZE, Ahi, Alo, Bhi, Blo,
                      rowBase, (kt + 1) * 64, t);
            CP_COMMIT();
        }
    }
    // wait for the last MMA (in-order tensor queue => all earlier done too)
    MBARRIER_WAIT_PARITY(sbase + 8 + ((nkt - 1) & 1) * 8, ((nkt - 1) >> 1) & 1);
    TCGEN05_FENCE_AFTER();

    float* Ds = reinterpret_cast<float*>(smem + 1024);
#pragma unroll 1
    for (int qr = 0; qr < 4; qr++) {
        uint32_t d0[32], d1[32];
        TCGEN05_LD_32X32B_X32(d0, tmem + qr * 64);
        TCGEN05_LD_32X32B_X32(d1, tmem + qr * 64 + 32);
        TCGEN05_WAIT_LD();
        __syncthreads();
#pragma unroll
        for (int j = 0; j < 32; j++) Ds[t * 65 + j] = __uint_as_float(d0[j]);
#pragma unroll
        for (int j = 0; j < 32; j++) Ds[t * 65 + 32 + j] = __uint_as_float(d1[j]);
        __syncthreads();

        const int cw = rowInW + qr * 64;
        int out_sel; const float* bias;
        if (mode == 0) { out_sel = w; bias = (w == 0) ? b0 : (w == 1) ? b1 : b2; }
        else           { out_sel = 3; bias = b0; }

        if (out_sel == 2) {
            const int hdl = t >> 1, sh = t & 1;
            const float bv = __ldg(&bias[cw + hdl]);
            const int hh = cw >> 6;
            const size_t dstoff = ((size_t)(bb * HH + hh) * HDD + hdl) * SS
                                  + (rowBase & 2047) + sh * 64;
#pragma unroll
            for (int c = 0; c < 4; c++) {
                uint32_t hp[8], lp[8];
#pragma unroll
                for (int e = 0; e < 8; e++) {
                    float v0 = Ds[(sh * 64 + c * 16 + e * 2 + 0) * 65 + hdl] + bv;
                    float v1 = Ds[(sh * 64 + c * 16 + e * 2 + 1) * 65 + hdl] + bv;
                    float h0 = __bfloat162float(__float2bfloat16(v0));
                    float h1 = __bfloat162float(__float2bfloat16(v1));
                    hp[e] = pack_bf16x2(h0, h1);
                    lp[e] = pack_bf16x2(v0 - h0, v1 - h1);
                }
                *reinterpret_cast<uint4*>(g_vthi + dstoff + c * 16)     = *reinterpret_cast<uint4*>(hp);
                *reinterpret_cast<uint4*>(g_vthi + dstoff + c * 16 + 8) = *reinterpret_cast<uint4*>(hp + 4);
                *reinterpret_cast<uint4*>(g_vtlo + dstoff + c * 16)     = *reinterpret_cast<uint4*>(lp);
                *reinterpret_cast<uint4*>(g_vtlo + dstoff + c * 16 + 8) = *reinterpret_cast<uint4*>(lp + 4);
            }
        } else {
            float vals[64];
#pragma unroll
            for (int j = 0; j < 64; j++) vals[j] = Ds[t * 65 + j];
            epi_store(out_sel, cw >> 6, bb, ss, gRow, cw, vals, bias, Y);
        }
    }

    __syncthreads();
    if (t == 0) { MBARRIER_INVAL(sbase + 8); MBARRIER_INVAL(sbase + 16); }
    __syncthreads();
    if (wid == 0) TCGEN05_DEALLOC(tmem, 256);

#else  // FFMA fallback (non-'a' targets; never runs on GB300)
    float* As = reinterpret_cast<float*>(smem + 1024);
    float* Bs = As + 128 * 33;

#pragma unroll 1
    for (int qr = 0; qr < 4; qr++) {
        float acc[64];
#pragma unroll
        for (int j = 0; j < 64; j++) acc[j] = 0.0f;

        for (int kt = 0; kt < DD / 32; kt++) {
            const int k0 = kt * 32;
            __syncthreads();
#pragma unroll
            for (int k = 0; k < 32; k++) {
                size_t gi = (size_t)(rowBase + t) * DD + k0 + k;
                As[t * 33 + k] = __bfloat162float(Ahi[gi]) + __bfloat162float(Alo[gi]);
            }
#pragma unroll
            for (int i = 0; i < 16; i++) {
                int idx = t * 16 + i;
                int k = idx >> 6, j = idx & 63;
                size_t gi = (size_t)(rowInW + qr * 64 + j) * DD + k0 + k;
                Bs[k * 64 + j] = __bfloat162float(g_wthi[w][gi]) + __bfloat162float(g_wtlo[w][gi]);
            }
            __syncthreads();
#pragma unroll
            for (int k = 0; k < 32; k++) {
                float a = As[t * 33 + k];
#pragma unroll
                for (int j = 0; j < 64; j++) acc[j] += a * Bs[k * 64 + j];
            }
        }
        const int cw = rowInW + qr * 64;
        int out_sel; const float* bias;
        if (mode == 0) { out_sel = w; bias = (w == 0) ? b0 : (w == 1) ? b1 : b2; }
        else           { out_sel = 3; bias = b0; }
        epi_store(out_sel, cw >> 6, bb, ss, gRow, cw, acc, bias, Y);
        __syncthreads();
    }
#endif
}

// ------- tensor-core causal attention, SELECTIVE split-K ----------------
// (unchanged from R14: issuer warp 8, per-buffer mbarriers, STTM P,
//  last-finisher in-kernel combine for split rows)
#define AT_QHI  1024
#define AT_QLO  (1024 + 16384)
#define AT_K0   (1024 + 32768)   // K buf b at +b*16384 (hi +0, lo +8192)
#define AT_V0   (1024 + 65536)   // V buf b at +b*16384 (hi +0, lo +8192)
#define AT_TOTAL (1024 + 98304)  // 99328 -> 2 CTAs/SM

__global__ __launch_bounds__(288, 2) void tc_attn()
{
    extern __shared__ char smem[];
    const int t = threadIdx.x;
    const int qt = gridDim.x - 1 - blockIdx.x;   // longest CTAs first
    const int h = blockIdx.y;
    const int b = blockIdx.z >> 1, sp = blockIdx.z & 1;
    const bool split = (qt >= SPLIT_QT);
    if (!split && sp == 1) return;               // empty CTA
    const size_t bh = (size_t)(b * HH + h);

    const int n = split ? (qt + 1) : (2 * qt + 2);
    const int ktBeg = split ? sp * n : 0;

#if HAS_TC
    const uint32_t sbase = smem_u32(smem);
    const int wid = t >> 5;          // 0..8
    const int lid = t & 31;
    const bool smx = (wid < 8);
    const int sub = wid & 3;
    const int ch  = wid >> 2;
    const int row = sub * 32 + lid;
    const int qi = qt * 128 + row;
    const uint32_t mbarS0 = sbase + 8;
    const uint32_t mbarS1 = sbase + 16;
    const uint32_t mbarP  = sbase + 24;
    const uint32_t warp_off = ((uint32_t)sub) << 21;

    if (wid == 0) { TCGEN05_ALLOC(sbase, 256); TCGEN05_RELINQUISH(); }
    if (t == 0) { MBARRIER_INIT(mbarS0, 1); MBARRIER_INIT(mbarS1, 1); MBARRIER_INIT(mbarP, 1); }
    __syncthreads();
    uint32_t tmem;
    asm volatile("ld.shared.b32 %0, [%1];" : "=r"(tmem) : "r"(sbase));
    const uint32_t tS0 = tmem;
    const uint32_t tS1 = tmem + 64;
    const uint32_t tO  = tmem + 128;
    const uint32_t tPH = tmem + 192;
    const uint32_t tPL = tmem + 224;

    // ---- prologue: Q tile + K/V(ktBeg) ----
    if (smx) {
        const uint4* qh = reinterpret_cast<const uint4*>(g_qhi + (bh * SS + (size_t)qt * 128) * HDD);
        const uint4* ql = reinterpret_cast<const uint4*>(g_qlo + (bh * SS + (size_t)qt * 128) * HDD);
#pragma unroll
        for (int i = 0; i < 4; i++) {
            int idx = i * 256 + t;
            int r = idx >> 3, slot = idx & 7;
            uint32_t off = SWZ128((uint32_t)(r * 128 + slot * 16));
            *reinterpret_cast<uint4*>(smem + AT_QHI + off) = qh[idx];
            *reinterpret_cast<uint4*>(smem + AT_QLO + off) = ql[idx];
        }
        const int kb0 = ktBeg * 64;
        const uint4* kh = reinterpret_cast<const uint4*>(g_khi + (bh * SS + kb0) * HDD);
        const uint4* kl = reinterpret_cast<const uint4*>(g_klo + (bh * SS + kb0) * HDD);
#pragma unroll
        for (int i = 0; i < 2; i++) {
            int idx = i * 256 + t;
            int r = idx >> 3, slot = idx & 7;
            uint32_t off = SWZ128((uint32_t)(r * 128 + slot * 16));
            *reinterpret_cast<uint4*>(smem + AT_K0 + off) = kh[idx];
            *reinterpret_cast<uint4*>(smem + AT_K0 + 8192 + off) = kl[idx];
            *reinterpret_cast<uint4*>(smem + AT_V0 + off) =
                reinterpret_cast<const uint4*>(g_vthi + (bh * HDD + r) * SS + kb0)[slot];
            *reinterpret_cast<uint4*>(smem + AT_V0 + 8192 + off) =
                reinterpret_cast<const uint4*>(g_vtlo + (bh * HDD + r) * SS + kb0)[slot];
        }
        FENCE_PROXY_ASYNC();
    }
    __syncthreads();

    const uint64_t dQhi = MAKE_SMEM_DESC(sbase + AT_QHI);
    const uint64_t dQlo = MAKE_SMEM_DESC(sbase + AT_QLO);

    // prologue: issue S(i=0) -> tS0
    if (wid == 8) {
        if (elect_one_pred()) {
            const uint64_t dKhi = MAKE_SMEM_DESC(sbase + AT_K0);
            const uint64_t dKlo = MAKE_SMEM_DESC(sbase + AT_K0 + 8192);
#pragma unroll
            for (int ks = 0; ks < 4; ks++) {
                const uint64_t off = ks * 2;
                mma_f16_ss(tS0, dQhi + off, dKhi + off, ATT_IDESC, ks != 0);
                mma_f16_ss(tS0, dQhi + off, dKlo + off, ATT_IDESC, true);
                mma_f16_ss(tS0, dQlo + off, dKhi + off, ATT_IDESC, true);
            }
            TCGEN05_COMMIT(mbarS0);
        }
    }

    float lpart = 0.0f;
    int phP = 0;

    for (int i = 0; i < n; i++) {
        const int kt = ktBeg + i;
        const bool pre = (i + 1 < n);
        uint4 pvh[2], pvl[2];

        // --- load warps: store K(i+1), prefetch V(i+1) ---
        if (smx && pre) {
            const int nb = (kt + 1) * 64;
            const uint32_t kb = AT_K0 + ((i + 1) & 1) * 16384;
            const uint4* kh = reinterpret_cast<const uint4*>(g_khi + (bh * SS + nb) * HDD);
            const uint4* kl = reinterpret_cast<const uint4*>(g_klo + (bh * SS + nb) * HDD);
#pragma unroll
            for (int j = 0; j < 2; j++) {
                int idx = j * 256 + t;
                int r = idx >> 3, slot = idx & 7;
                uint32_t off = SWZ128((uint32_t)(r * 128 + slot * 16));
                *reinterpret_cast<uint4*>(smem + kb + off) = kh[idx];
                *reinterpret_cast<uint4*>(smem + kb + 8192 + off) = kl[idx];
                pvh[j] = reinterpret_cast<const uint4*>(g_vthi + (bh * HDD + r) * SS + nb)[slot];
                pvl[j] = reinterpret_cast<const uint4*>(g_vtlo + (bh * HDD + r) * SS + nb)[slot];
            }
            FENCE_PROXY_ASYNC();
        }
        __syncthreads();   // the ONLY sync per iteration

        if (wid == 8) {
            // ---- issuer warp: PV(i-1) first, then S(i+1) ----
            if (elect_one_pred()) {
                TCGEN05_FENCE_AFTER();
                if (i > 0) {
                    const uint32_t vb = sbase + AT_V0 + ((i - 1) & 1) * 16384;
                    const uint64_t dVhi = MAKE_SMEM_DESC(vb);
                    const uint64_t dVlo = MAKE_SMEM_DESC(vb + 8192);
#pragma unroll
                    for (int ks = 0; ks < 4; ks++) {
                        const uint64_t off = ks * 2;
                        const bool first = (i == 1) && (ks == 0);
                        mma_f16_ts(tO, tPH + ks * 8, dVhi + off, ATT_IDESC, !first);
                        mma_f16_ts(tO, tPH + ks * 8, dVlo + off, ATT_IDESC, true);
                        mma_f16_ts(tO, tPL + ks * 8, dVhi + off, ATT_IDESC, true);
                    }
                    TCGEN05_COMMIT(mbarP);
                }
                if (pre) {
                    const uint32_t kb = sbase + AT_K0 + ((i + 1) & 1) * 16384;
                    const uint64_t dKhi = MAKE_SMEM_DESC(kb);
                    const uint64_t dKlo = MAKE_SMEM_DESC(kb + 8192);
                    const uint32_t tSn = ((i + 1) & 1) ? tS1 : tS0;
#pragma unroll
                    for (int ks = 0; ks < 4; ks++) {
                        const uint64_t off = ks * 2;
                        mma_f16_ss(tSn, dQhi + off, dKhi + off, ATT_IDESC, ks != 0);
                        mma_f16_ss(tSn, dQhi + off, dKlo + off, ATT_IDESC, true);
                        mma_f16_ss(tSn, dQlo + off, dKhi + off, ATT_IDESC, true);
                    }
                    TCGEN05_COMMIT(((i + 1) & 1) ? mbarS1 : mbarS0);
                }
            }
        } else {
            // ---- softmax warps ----
            MBARRIER_WAIT_PARITY((i & 1) ? mbarS1 : mbarS0, (i >> 1) & 1);
            TCGEN05_FENCE_AFTER();

            float s_[32];
            {
                const uint32_t tSc = ((i & 1) ? tS1 : tS0) + ch * 32;
                TCGEN05_LD_32X32B_X32(reinterpret_cast<uint32_t*>(s_), tSc);
            }
            TCGEN05_WAIT_LD();

            const int cb0 = kt * 64 + ch * 32;
            if (kt >= 2 * qt) {
#pragma unroll
                for (int j = 0; j < 32; j++)
                    if (cb0 + j > qi) s_[j] = -1e30f;
            }
            float sum = 0.0f;
#pragma unroll
            for (int j = 0; j < 32; j++) {
                float e = (j % 3 == 0) ? exp2_poly(s_[j]) : ex2_mufu(s_[j]);
                s_[j] = e;
                sum += e;
            }
            lpart += sum;

            if (i > 0) { MBARRIER_WAIT_PARITY(mbarP, phP & 1); phP++; }

            // split P -> bf16 hi/lo straight into TMEM
            {
                uint32_t hw[16], lw[16];
#pragma unroll
                for (int g = 0; g < 16; g++) {
                    float p0 = s_[g*2+0], p1 = s_[g*2+1];
                    float h0 = __bfloat162float(__float2bfloat16(p0));
                    float h1 = __bfloat162float(__float2bfloat16(p1));
                    hw[g] = pack_bf16x2(h0, h1);
                    lw[g] = pack_bf16x2(p0 - h0, p1 - h1);
                }
                TCGEN05_ST_32X32B_X16(tPH + ch * 16 + warp_off, hw);
                TCGEN05_ST_32X32B_X16(tPL + ch * 16 + warp_off, lw);
                TCGEN05_WAIT_ST();
            }
            TCGEN05_FENCE_BEFORE();

            // store V(i+1) (buffer free: PV(i-1) waited above)
            if (pre) {
                const uint32_t vb = AT_V0 + ((i + 1) & 1) * 16384;
#pragma unroll
                for (int j = 0; j < 2; j++) {
                    int idx = j * 256 + t;
                    int r = idx >> 3, slot = idx & 7;
                    uint32_t off = SWZ128((uint32_t)(r * 128 + slot * 16));
                    *reinterpret_cast<uint4*>(smem + vb + off) = pvh[j];
                    *reinterpret_cast<uint4*>(smem + vb + 8192 + off) = pvl[j];
                }
                FENCE_PROXY_ASYNC();
            }
        }
    }

    // ---- tail: issue final PV(n-1) ----
    __syncthreads();
    if (wid == 8) {
        if (elect_one_pred()) {
            TCGEN05_FENCE_AFTER();
            const uint32_t vb = sbase + AT_V0 + ((n - 1) & 1) * 16384;
            const uint64_t dVhi = MAKE_SMEM_DESC(vb);
            const uint64_t dVlo = MAKE_SMEM_DESC(vb + 8192);
#pragma unroll
            for (int ks = 0; ks < 4; ks++) {
                const uint64_t off = ks * 2;
                const bool first = (n == 1) && (ks == 0);
                mma_f16_ts(tO, tPH + ks * 8, dVhi + off, ATT_IDESC, !first);
                mma_f16_ts(tO, tPH + ks * 8, dVlo + off, ATT_IDESC, true);
                mma_f16_ts(tO, tPL + ks * 8, dVhi + off, ATT_IDESC, true);
            }
            TCGEN05_COMMIT(mbarP);
        }
    }

    MBARRIER_WAIT_PARITY(mbarP, (n - 1) & 1);
    TCGEN05_FENCE_AFTER();

    // ---- epilogue ----
    if (smx) {
        float* sums = reinterpret_cast<float*>(smem + AT_QHI);
        sums[ch * 128 + row] = lpart;
    }
    __syncthreads();

    if (smx) {
        float O[32];
        TCGEN05_LD_32X32B_X32(reinterpret_cast<uint32_t*>(O), tO + ch * 32);
        TCGEN05_WAIT_LD();

        const float* sums = reinterpret_cast<const float*>(smem + AT_QHI);
        const float ltot = sums[row] + sums[128 + row];

        if (split) {
            const size_t prow = bh * SS + qi;
            if (ch == 0) g_lp[sp][prow] = ltot;
            float* dst = g_po + ((size_t)sp * NROWS_ATT + prow) * HDD + ch * 32;
#pragma unroll
            for (int g = 0; g < 8; g++)
                *reinterpret_cast<float4*>(dst + g * 4) = *reinterpret_cast<float4*>(O + g * 4);
        } else {
            const float inv = 1.0f / ltot;
            size_t ob = ((size_t)b * SS + qi) * DD + h * HDD + ch * 32;
#pragma unroll
            for (int g = 0; g < 4; g++) {
                uint32_t hw[4], lw[4];
#pragma unroll
                for (int e2 = 0; e2 < 4; e2++) {
                    float v0 = O[g*8 + e2*2+0] * inv;
                    float v1 = O[g*8 + e2*2+1] * inv;
                    float h0 = __bfloat162float(__float2bfloat16(v0));
                    float h1 = __bfloat162float(__float2bfloat16(v1));
                    hw[e2] = pack_bf16x2(h0, h1);
                    lw[e2] = pack_bf16x2(v0 - h0, v1 - h1);
                }
                *reinterpret_cast<uint4*>(g_chi + ob + g*8) = *reinterpret_cast<uint4*>(hw);
                *reinterpret_cast<uint4*>(g_clo + ob + g*8) = *reinterpret_cast<uint4*>(lw);
            }
        }
    }

    // ---- last-finisher combine (split rows only) ----
    if (split) {
        __threadfence();
        __syncthreads();
        int* sflag = reinterpret_cast<int*>(smem + 32);
        if (t == 0) {
            const int fidx = (int)bh * (16 - SPLIT_QT) + (qt - SPLIT_QT);
            *sflag = atomicAdd(&g_flag[fidx], 1);
        }
        __syncthreads();
        if (*sflag == 1 && smx) {
            const size_t prow = bh * SS + qi;
            const float inv = 1.0f / (g_lp[0][prow] + g_lp[1][prow]);
            const float4* p0 = reinterpret_cast<const float4*>(g_po + prow * HDD + ch * 32);
            const float4* p1 = reinterpret_cast<const float4*>(
                g_po + ((size_t)NROWS_ATT + prow) * HDD + ch * 32);
            size_t ob = ((size_t)b * SS + qi) * DD + h * HDD + ch * 32;
#pragma unroll
            for (int g = 0; g < 4; g++) {
                float4 a0 = p0[g*2+0], a1 = p0[g*2+1];
                float4 c0 = p1[g*2+0], c1 = p1[g*2+1];
                float v[8];
                v[0] = (a0.x + c0.x) * inv; v[1] = (a0.y + c0.y) * inv;
                v[2] = (a0.z + c0.z) * inv; v[3] = (a0.w + c0.w) * inv;
                v[4] = (a1.x + c1.x) * inv; v[5] = (a1.y + c1.y) * inv;
                v[6] = (a1.z + c1.z) * inv; v[7] = (a1.w + c1.w) * inv;
                uint32_t hw[4], lw[4];
#pragma unroll
                for (int e = 0; e < 4; e++) {
                    float h0 = __bfloat162float(__float2bfloat16(v[e*2+0]));
                    float h1 = __bfloat162float(__float2bfloat16(v[e*2+1]));
                    hw[e] = pack_bf16x2(h0, h1);
                    lw[e] = pack_bf16x2(v[e*2+0] - h0, v[e*2+1] - h1);
                }
                *reinterpret_cast<uint4*>(g_chi + ob + g*8) = *reinterpret_cast<uint4*>(hw);
                *reinterpret_cast<uint4*>(g_clo + ob + g*8) = *reinterpret_cast<uint4*>(lw);
            }
        }
    }

    __syncthreads();
    if (t == 0) { MBARRIER_INVAL(mbarS0); MBARRIER_INVAL(mbarS1); MBARRIER_INVAL(mbarP); }
    __syncthreads();
    if (wid == 0) TCGEN05_DEALLOC(tmem, 256);

#else  // scalar fallback (never runs on GB300)
    __shared__ int sflag2;
    if (t < 128) {
        const int qi2 = qt * 128 + t;
        float q[64];
#pragma unroll
        for (int d = 0; d < 64; d++) {
            size_t o = (bh * SS + qi2) * HDD + d;
            q[d] = __bfloat162float(g_qhi[o]) + __bfloat162float(g_qlo[o]);
        }
        float O[64];
#pragma unroll
        for (int d = 0; d < 64; d++) O[d] = 0.0f;
        float l = 0.0f;
        const int kLo = ktBeg * 64;
        const int kHi = (ktBeg + n) * 64 - 1;
        const int kEnd = (qi2 < kHi) ? qi2 : kHi;
        for (int k = kLo; k <= kEnd; k++) {
            float s = 0.0f;
            size_t kb = (bh * SS + k) * HDD;
            for (int d = 0; d < 64; d++)
                s += q[d] * (__bfloat162float(g_khi[kb + d]) + __bfloat162float(g_klo[kb + d]));
            float p = exp2f(s);
            l += p;
            for (int d = 0; d < 64; d++) {
                size_t vo = (bh * HDD + d) * SS + k;
                O[d] += p * (__bfloat162float(g_vthi[vo]) + __bfloat162float(g_vtlo[vo]));
            }
        }
        if (split) {
            const size_t prow = bh * SS + qi2;
            g_lp[sp][prow] = l;
            float* dst = g_po + ((size_t)sp * NROWS_ATT + prow) * HDD;
            for (int d = 0; d < 64; d++) dst[d] = O[d];
        } else {
            const float inv = 1.0f / l;
            size_t ob = ((size_t)b * SS + qi2) * DD + h * HDD;
            for (int d = 0; d < 64; d++) {
                float v = O[d] * inv;
                __nv_bfloat16 hb = __float2bfloat16(v);
                g_chi[ob + d] = hb;
                g_clo[ob + d] = __float2bfloat16(v - __bfloat162float(hb));
            }
        }
    }
    if (split) {
        __threadfence();
        __syncthreads();
        if (t == 0) {
            const int fidx = (int)bh * (16 - SPLIT_QT) + (qt - SPLIT_QT);
            sflag2 = atomicAdd(&g_flag[fidx], 1);
        }
        __syncthreads();
        if (sflag2 == 1 && t < 128) {
            const int qi2 = qt * 128 + t;
            const size_t prow = bh * SS + qi2;
            const float inv = 1.0f / (g_lp[0][prow] + g_lp[1][prow]);
            size_t ob = ((size_t)b * SS + qi2) * DD + h * HDD;
            for (int d = 0; d < 64; d++) {
                float v = (g_po[prow * HDD + d] + g_po[(size_t)NROWS_ATT * HDD + prow * HDD + d]) * inv;
                __nv_bfloat16 hb = __float2bfloat16(v);
                g_chi[ob + d] = hb;
                g_clo[ob + d] = __float2bfloat16(v - __bfloat162float(hb));
            }
        }
    }
#endif
}

// ---------------------------------------------------------------------------
extern "C" void kernel_launch(void* const* d_in, const int* in_sizes, int n_in,
                              void* d_out, int out_size)
{
    const float* x  = (const float*)d_in[0];
    const float* wq = (const float*)d_in[1];
    const float* bq = (const float*)d_in[2];
    const float* wk = (const float*)d_in[3];
    const float* bk = (const float*)d_in[4];
    const float* wv = (const float*)d_in[5];
    const float* bv = (const float*)d_in[6];
    const float* wo = (const float*)d_in[7];
    const float* bo = (const float*)d_in[8];
    float* out = (float*)d_out;

    cudaFuncSetAttribute(tc_gemm, cudaFuncAttributeMaxDynamicSharedMemorySize, GM_TOTAL);
    cudaFuncSetAttribute(tc_attn, cudaFuncAttributeMaxDynamicSharedMemorySize, AT_TOTAL);

    // fused prep: weight transpose+split (2304 blocks) + x split (6144 blocks)
    prep_kernel<<<8448, 256>>>(x, wq, wk, wv, wo);

    // fused QKV: N = 2304 -> 9 col-blocks of 256
    tc_gemm<<<dim3(9, MROWS / 128), 128, GM_TOTAL>>>(bq, bk, bv, nullptr, 0, 0);

    // selective split-K attention with in-kernel last-finisher combine
    tc_attn<<<dim3(SS / 128, HH, BB * 2), 288, AT_TOTAL>>>();

    // O-projection: N = 768 -> 3 col-blocks of 256
    tc_gemm<<<dim3(3, MROWS / 128), 128, GM_TOTAL>>>(bo, bo, bo, out, 1, 1);
}

// round 16
// speedup vs baseline: 1.0029x; 1.0029x over previous
#include <cuda_runtime.h>
#include <cuda_bf16.h>
#include <cstdint>

#define BB 2
#define SS 2048
#define DD 768
#define HH 12
#define HDD 64
#define MROWS (BB*SS)   // 4096
#define NROWS_ATT (BB*HH*SS)   // 49152
#define SPLIT_QT 8      // split key range for qt >= SPLIT_QT

#if defined(__CUDA_ARCH__) && \
    ((__CUDA_ARCH__ == 1030 && defined(__CUDA_ARCH_FEAT_SM103_ALL)) || \
     (__CUDA_ARCH__ == 1000 && defined(__CUDA_ARCH_FEAT_SM100_ALL)) || \
     (__CUDA_ARCH__ == 1010 && defined(__CUDA_ARCH_FEAT_SM101_ALL)))
#define HAS_TC 1
#else
#define HAS_TC 0
#endif

// log2(e) folded into Q so softmax uses exp2
#define QSCALE 0.18033688011112042f   // 0.125 * log2(e)

// ---------------- device scratch (allocation-free rule) ----------------
__device__ __nv_bfloat16 g_xhi[MROWS*DD], g_xlo[MROWS*DD];
__device__ __nv_bfloat16 g_chi[MROWS*DD], g_clo[MROWS*DD];
__device__ __nv_bfloat16 g_wthi[4][DD*DD], g_wtlo[4][DD*DD];   // [N][K]
__device__ __nv_bfloat16 g_qhi[BB*HH*SS*HDD], g_qlo[BB*HH*SS*HDD];
__device__ __nv_bfloat16 g_khi[BB*HH*SS*HDD], g_klo[BB*HH*SS*HDD];
__device__ __nv_bfloat16 g_vthi[BB*HH*SS*HDD], g_vtlo[BB*HH*SS*HDD];
// split-K attention partials (only qt >= SPLIT_QT rows)
__device__ float g_po[2ull*NROWS_ATT*HDD];
__device__ float g_lp[2][NROWS_ATT];
__device__ int   g_flag[BB*HH*(16 - SPLIT_QT)];   // 192 finisher flags

// ---------------- PTX helpers ------------------------------------------
__device__ __forceinline__ uint32_t smem_u32(const void* p) {
    uint32_t a;
    asm("{ .reg .u64 t; cvta.to.shared.u64 t, %1; cvt.u32.u64 %0, t; }" : "=r"(a) : "l"(p));
    return a;
}
__device__ __forceinline__ float ex2_mufu(float x) {
    float r; asm("ex2.approx.f32 %0, %1;" : "=f"(r) : "f"(x)); return r;
}
// exp2 via FMA pipe: magic-constant floor + degree-4 poly on [-0.5, 0.5]
__device__ __forceinline__ float exp2_poly(float y) {
    y = fmaxf(y, -125.0f);
    float z = y + 12582912.0f;
    float f = y - (z - 12582912.0f);
    int   n = __float_as_int(z) - 0x4B400000;
    float p = 0.0096181291f;
    p = fmaf(p, f, 0.0555041087f);
    p = fmaf(p, f, 0.2402265069f);
    p = fmaf(p, f, 0.6931471806f);
    p = fmaf(p, f, 1.0f);
    return __int_as_float(__float_as_int(p) + (n << 23));
}

#if HAS_TC
__device__ __forceinline__ uint32_t elect_one_pred() {
    uint32_t pred;
    asm volatile(
        "{\n\t.reg .pred p;\n\telect.sync _|p, 0xFFFFFFFF;\n\tselp.b32 %0, 1, 0, p;\n\t}"
        : "=r"(pred));
    return pred;
}

#define TCGEN05_ALLOC(smem_result_addr, nCols) \
    asm volatile("tcgen05.alloc.cta_group::1.sync.aligned.shared::cta.b32 [%0], %1;" \
                 :: "r"((uint32_t)(smem_result_addr)), "r"((uint32_t)(nCols)) : "memory")
#define TCGEN05_DEALLOC(tmem_addr, nCols) \
    asm volatile("tcgen05.dealloc.cta_group::1.sync.aligned.b32 %0, %1;" \
                 :: "r"(tmem_addr), "r"((uint32_t)(nCols)))
#define TCGEN05_RELINQUISH() \
    asm volatile("tcgen05.relinquish_alloc_permit.cta_group::1.sync.aligned;")
#define TCGEN05_COMMIT(mbar) \
    asm volatile("tcgen05.commit.cta_group::1.mbarrier::arrive::one.shared::cluster.b64 [%0];" \
                 :: "r"((uint32_t)(mbar)) : "memory")
#define TCGEN05_WAIT_LD() asm volatile("tcgen05.wait::ld.sync.aligned;" ::: "memory")
#define TCGEN05_WAIT_ST() asm volatile("tcgen05.wait::st.sync.aligned;" ::: "memory")
#define TCGEN05_FENCE_AFTER() asm volatile("tcgen05.fence::after_thread_sync;" ::: "memory")
#define TCGEN05_FENCE_BEFORE() asm volatile("tcgen05.fence::before_thread_sync;" ::: "memory")
#define FENCE_PROXY_ASYNC() asm volatile("fence.proxy.async.shared::cta;" ::: "memory")

#define MBARRIER_INIT(mbar, count) \
    asm volatile("mbarrier.init.shared.b64 [%0], %1;" \
                 :: "r"((uint32_t)(mbar)), "r"((uint32_t)(count)) : "memory")
#define MBARRIER_INVAL(mbar) \
    asm volatile("mbarrier.inval.shared.b64 [%0];" :: "r"((uint32_t)(mbar)) : "memory")

#define MBARRIER_WAIT_PARITY(mbar_smem_addr, phase_parity) do { \
    uint32_t _mbar = (uint32_t)(mbar_smem_addr); \
    uint32_t _parity = (uint32_t)(phase_parity); \
    uint32_t _done; \
    asm volatile( \
        "{\n\t.reg .pred p;\n\t" \
        "mbarrier.try_wait.parity.acquire.cta.shared::cta.b64 p, [%1], %2;\n\t" \
        "selp.b32 %0, 1, 0, p;\n\t}" \
        : "=r"(_done) : "r"(_mbar), "r"(_parity) : "memory"); \
    if (!_done) { \
        asm volatile( \
            "{\n\t.reg .pred P1;\n\t" \
            "WAIT_LOOP_%=:\n\t" \
            "mbarrier.try_wait.parity.acquire.cta.shared::cta.b64 P1, [%0], %1, 0x989680;\n\t" \
            "@P1 bra.uni WAIT_DONE_%=;\n\t" \
            "bra.uni WAIT_LOOP_%=;\n\t" \
            "WAIT_DONE_%=:\n\t}" \
            :: "r"(_mbar), "r"(_parity) : "memory"); \
    } \
} while(0)

#define TCGEN05_LD_32X32B_X32(r, tmem_addr) \
    asm volatile( \
        "tcgen05.ld.sync.aligned.32x32b.x32.b32 " \
        "{%0, %1, %2, %3, %4, %5, %6, %7, " \
        " %8, %9, %10, %11, %12, %13, %14, %15, " \
        " %16, %17, %18, %19, %20, %21, %22, %23, " \
        " %24, %25, %26, %27, %28, %29, %30, %31}, [%32];" \
        : "=r"((r)[0]),  "=r"((r)[1]),  "=r"((r)[2]),  "=r"((r)[3]), \
          "=r"((r)[4]),  "=r"((r)[5]),  "=r"((r)[6]),  "=r"((r)[7]), \
          "=r"((r)[8]),  "=r"((r)[9]),  "=r"((r)[10]), "=r"((r)[11]), \
          "=r"((r)[12]), "=r"((r)[13]), "=r"((r)[14]), "=r"((r)[15]), \
          "=r"((r)[16]), "=r"((r)[17]), "=r"((r)[18]), "=r"((r)[19]), \
          "=r"((r)[20]), "=r"((r)[21]), "=r"((r)[22]), "=r"((r)[23]), \
          "=r"((r)[24]), "=r"((r)[25]), "=r"((r)[26]), "=r"((r)[27]), \
          "=r"((r)[28]), "=r"((r)[29]), "=r"((r)[30]), "=r"((r)[31]) \
        : "r"(tmem_addr))

#define TCGEN05_ST_32X32B_X16(tmem_addr, r) \
    asm volatile( \
        "tcgen05.st.sync.aligned.32x32b.x16.b32 [%0], " \
        "{%1, %2, %3, %4, %5, %6, %7, %8, " \
        " %9, %10, %11, %12, %13, %14, %15, %16};" \
        :: "r"(tmem_addr), \
           "r"((r)[0]),  "r"((r)[1]),  "r"((r)[2]),  "r"((r)[3]), \
           "r"((r)[4]),  "r"((r)[5]),  "r"((r)[6]),  "r"((r)[7]), \
           "r"((r)[8]),  "r"((r)[9]),  "r"((r)[10]), "r"((r)[11]), \
           "r"((r)[12]), "r"((r)[13]), "r"((r)[14]), "r"((r)[15]) \
        : "memory")

#define CP_ASYNC16(dst, src) \
    asm volatile("cp.async.cg.shared.global [%0], [%1], 16;" :: "r"(dst), "l"(src) : "memory")
#define CP_COMMIT() asm volatile("cp.async.commit_group;" ::: "memory")
#define CP_WAIT(n)  asm volatile("cp.async.wait_group %0;" :: "n"(n) : "memory")

__device__ __forceinline__ void mma_f16_ss(uint32_t d_tmem, uint64_t a_desc, uint64_t b_desc,
                                           uint32_t idesc, bool acc) {
    uint32_t en = acc ? 1u : 0u;
    uint32_t zero = 0u;
    asm volatile(
        "{\n\t.reg .pred p;\n\t"
        "setp.ne.u32 p, %5, 0;\n\t"
        "tcgen05.mma.cta_group::1.kind::f16 [%0], %1, %2, %3, {%4, %4, %4, %4}, p;\n\t}"
        :: "r"(d_tmem), "l"(a_desc), "l"(b_desc), "r"(idesc), "r"(zero), "r"(en)
        : "memory");
}

// TS form: A in TMEM
__device__ __forceinline__ void mma_f16_ts(uint32_t d_tmem, uint32_t a_tmem, uint64_t b_desc,
                                           uint32_t idesc, bool acc) {
    uint32_t en = acc ? 1u : 0u;
    uint32_t zero = 0u;
    asm volatile(
        "{\n\t.reg .pred p;\n\t"
        "setp.ne.u32 p, %5, 0;\n\t"
        "tcgen05.mma.cta_group::1.kind::f16 [%0], [%1], %2, %3, {%4, %4, %4, %4}, p;\n\t}"
        :: "r"(d_tmem), "r"(a_tmem), "l"(b_desc), "r"(idesc), "r"(zero), "r"(en)
        : "memory");
}
#endif  // HAS_TC

// SW128 (128B rows)
static constexpr uint64_t SMEM_DESC_BASE_SW128 =
    (uint64_t(2) << 61) | (uint64_t(1) << 46) | (uint64_t(64) << 32) | (uint64_t(1) << 16);
#define MAKE_SMEM_DESC(addr) (SMEM_DESC_BASE_SW128 | ((uint64_t)((addr) >> 4) & 0x3FFF))
#define SWZ128(off) ((off) ^ (((off) >> 3) & 0x70))

static constexpr uint32_t GEMM_IDESC =            // M=128, N=128
    (1u << 4) | (1u << 7) | (1u << 10) | (16u << 17) | (8u << 24);
static constexpr uint32_t ATT_IDESC =             // M=128, N=64
    (1u << 4) | (1u << 7) | (1u << 10) | (8u << 17) | (8u << 24);

__device__ __forceinline__ uint32_t pack_bf16x2(float a, float b) {
    __nv_bfloat162 t2 = __floats2bfloat162_rn(a, b);
    return *reinterpret_cast<uint32_t*>(&t2);
}

// -------- fused prep: weight transpose+split, x split, flag zero --------
__global__ void prep_kernel(const float* __restrict__ x,
                            const float* __restrict__ w0, const float* __restrict__ w1,
                            const float* __restrict__ w2, const float* __restrict__ w3)
{
    __shared__ float tile[32][33];
    const int bx = blockIdx.x;
    const int tid = threadIdx.x;
    if (bx == 0 && tid < BB*HH*(16 - SPLIT_QT)) g_flag[tid] = 0;

    if (bx < 2304) {
        const int widx = bx / 576;
        const int r = bx - widx * 576;
        const int n0 = (r % 24) * 32, k0 = (r / 24) * 32;
        const float* src = (widx == 0) ? w0 : (widx == 1) ? w1 : (widx == 2) ? w2 : w3;
        const int tx = tid & 31, ty = tid >> 5;   // (32, 8)
#pragma unroll
        for (int rr = 0; rr < 4; rr++)
            tile[ty + rr * 8][tx] = src[(k0 + ty + rr * 8) * DD + n0 + tx];
        __syncthreads();
        __nv_bfloat16* hiT = g_wthi[widx];
        __nv_bfloat16* loT = g_wtlo[widx];
#pragma unroll
        for (int rr = 0; rr < 4; rr++) {
            float v = tile[tx][ty + rr * 8];
            __nv_bfloat16 h = __float2bfloat16(v);
            int o = (n0 + ty + rr * 8) * DD + k0 + tx;
            hiT[o] = h;
            loT[o] = __float2bfloat16(v - __bfloat162float(h));
        }
    } else {
        const int i = (bx - 2304) * 256 + tid;
        float2 v = reinterpret_cast<const float2*>(x)[i];
        __nv_bfloat16 h0 = __float2bfloat16(v.x);
        __nv_bfloat16 h1 = __float2bfloat16(v.y);
        __nv_bfloat162 hp; hp.x = h0; hp.y = h1;
        __nv_bfloat162 lp;
        lp.x = __float2bfloat16(v.x - __bfloat162float(h0));
        lp.y = __float2bfloat16(v.y - __bfloat162float(h1));
        reinterpret_cast<__nv_bfloat162*>(g_xhi)[i] = hp;
        reinterpret_cast<__nv_bfloat162*>(g_xlo)[i] = lp;
    }
}

// ---------------- shared epilogue writer (Q/K/Y paths) ------------------
__device__ __forceinline__ void epi_store(int out_sel, int hh, int bb, int ss, int gRow,
                                          int cw, const float* vals,
                                          const float* __restrict__ bias, float* Y)
{
    if (out_sel == 3) {
        float* dst = Y + (size_t)gRow * DD + cw;
#pragma unroll
        for (int g = 0; g < 16; g++) {
            float4 o;
            o.x = vals[g*4+0] + __ldg(&bias[cw + g*4+0]);
            o.y = vals[g*4+1] + __ldg(&bias[cw + g*4+1]);
            o.z = vals[g*4+2] + __ldg(&bias[cw + g*4+2]);
            o.w = vals[g*4+3] + __ldg(&bias[cw + g*4+3]);
            *reinterpret_cast<float4*>(dst + g*4) = o;
        }
    } else if (out_sel <= 1) {
        __nv_bfloat16* Hi = out_sel ? g_khi : g_qhi;
        __nv_bfloat16* Lo = out_sel ? g_klo : g_qlo;
        const float sc = out_sel ? 1.0f : QSCALE;
        size_t ob = ((size_t)(bb * HH + hh) * SS + ss) * HDD;
#pragma unroll
        for (int g = 0; g < 8; g++) {
            uint32_t hw[4], lw[4];
#pragma unroll
            for (int e2 = 0; e2 < 4; e2++) {
                float v0 = (vals[g*8 + e2*2+0] + __ldg(&bias[cw + g*8 + e2*2+0])) * sc;
                float v1 = (vals[g*8 + e2*2+1] + __ldg(&bias[cw + g*8 + e2*2+1])) * sc;
                float h0 = __bfloat162float(__float2bfloat16(v0));
                float h1 = __bfloat162float(__float2bfloat16(v1));
                hw[e2] = pack_bf16x2(h0, h1);
                lw[e2] = pack_bf16x2(v0 - h0, v1 - h1);
            }
            *reinterpret_cast<uint4*>(Hi + ob + g*8) = *reinterpret_cast<uint4*>(hw);
            *reinterpret_cast<uint4*>(Lo + ob + g*8) = *reinterpret_cast<uint4*>(lw);
        }
    } else {
        size_t vb = (size_t)(bb * HH + hh) * HDD;
#pragma unroll
        for (int j = 0; j < 64; j++) {
            float v = vals[j] + __ldg(&bias[cw + j]);
            __nv_bfloat16 hb = __float2bfloat16(v);
            size_t o = (vb + j) * SS + ss;
            g_vthi[o] = hb;
            g_vtlo[o] = __float2bfloat16(v - __bfloat162float(hb));
        }
    }
}

// ---- GEMM: CTA 128x256, k-tile 64 (SW128), pipelined mainloop ----------
// MMA(kt) issued FIRST each iteration; then (under cover of MMA(kt), 1536
// cyc) wait MMA(kt-1), fill(kt+1), and CP_WAIT its landing. Tensor queue
// never drains AND fill latency is hidden (R15 exposed it at loop top).
#define GB_AHI 0
#define GB_ALO 16384
#define GB_BHI 32768
#define GB_BLO 65536
#define GB_SIZE 98304
#define GM_TOTAL (1024 + 2*GB_SIZE)   // 197632

#if HAS_TC
__device__ __forceinline__ void gemm_fill(uint32_t buf,
                                          const __nv_bfloat16* __restrict__ Ahi,
                                          const __nv_bfloat16* __restrict__ Alo,
                                          const __nv_bfloat16* __restrict__ Bhi,
                                          const __nv_bfloat16* __restrict__ Blo,
                                          int rowBase, int k0, int t)
{
#pragma unroll
    for (int i = 0; i < 8; i++) {          // A: 128 rows x 64 k
        int idx = i * 128 + t;
        int r = idx >> 3, s = idx & 7;
        size_t g = (size_t)(rowBase + r) * DD + k0 + s * 8;
        uint32_t off = SWZ128((uint32_t)(r * 128 + s * 16));
        CP_ASYNC16(buf + GB_AHI + off, (const char*)(Ahi + g));
        CP_ASYNC16(buf + GB_ALO + off, (const char*)(Alo + g));
    }
#pragma unroll
    for (int i = 0; i < 16; i++) {         // B: 256 rows x 64 k
        int idx = i * 128 + t;
        int r = idx >> 3, s = idx & 7;
        size_t g = (size_t)r * DD + k0 + s * 8;
        uint32_t off = SWZ128((uint32_t)(r * 128 + s * 16));
        CP_ASYNC16(buf + GB_BHI + off, (const char*)(Bhi + g));
        CP_ASYNC16(buf + GB_BLO + off, (const char*)(Blo + g));
    }
}
#endif

__global__ __launch_bounds__(128) void tc_gemm(
    const float* __restrict__ b0, const float* __restrict__ b1, const float* __restrict__ b2,
    float* __restrict__ Y, int in_sel, int mode)  // mode 0 = fused QKV, 1 = O-proj
{
    extern __shared__ char smem[];
    const int t = threadIdx.x;
    const int cb = blockIdx.x;
    const int rowBase = blockIdx.y * 128;

    int w, rowInW;
    if (mode == 0) { w = cb / 3; rowInW = (cb - w * 3) * 256; }
    else           { w = 3;      rowInW = cb * 256; }

    const __nv_bfloat16* Ahi = in_sel ? g_chi : g_xhi;
    const __nv_bfloat16* Alo = in_sel ? g_clo : g_xlo;
    const __nv_bfloat16* Bhi = g_wthi[w] + (size_t)rowInW * DD;
    const __nv_bfloat16* Blo = g_wtlo[w] + (size_t)rowInW * DD;

    const int gRow = rowBase + t;
    const int bb = gRow >> 11, ss = gRow & 2047;

#if HAS_TC
    const uint32_t sbase = smem_u32(smem);
    const int wid = t >> 5;

    if (wid == 0) { TCGEN05_ALLOC(sbase, 256); TCGEN05_RELINQUISH(); }
    if (t == 0) { MBARRIER_INIT(sbase + 8, 1); MBARRIER_INIT(sbase + 16, 1); }
    __syncthreads();
    uint32_t tmem;
    asm volatile("ld.shared.b32 %0, [%1];" : "=r"(tmem) : "r"(sbase));

    const int nkt = DD / 64;   // 12
    // prologue: fill(0) and wait for it
    gemm_fill(sbase + 1024, Ahi, Alo, Bhi, Blo, rowBase, 0, t);
    CP_COMMIT();
    CP_WAIT(0);
    FENCE_PROXY_ASYNC();
    __syncthreads();

    for (int kt = 0; kt < nkt; kt++) {
        const uint32_t buf = sbase + 1024 + (kt & 1) * GB_SIZE;

        // issue MMA(kt) FIRST — fill(kt) is complete+visible (end of prev iter)
        if (wid == 0) {
            if (elect_one_pred()) {
                const uint64_t dAhi = MAKE_SMEM_DESC(buf + GB_AHI);
                const uint64_t dAlo = MAKE_SMEM_DESC(buf + GB_ALO);
                const uint64_t dBhi = MAKE_SMEM_DESC(buf + GB_BHI);
                const uint64_t dBlo = MAKE_SMEM_DESC(buf + GB_BLO);
#pragma unroll
                for (int ks = 0; ks < 4; ks++) {
#pragma unroll
                    for (int nh = 0; nh < 2; nh++) {
                        const uint64_t ao = ks * 2;
                        const uint64_t bo = nh * 1024 + ks * 2;
                        const bool first = (kt == 0) && (ks == 0);
                        mma_f16_ss(tmem + nh * 128, dAhi + ao, dBhi + bo, GEMM_IDESC, !first);
                        mma_f16_ss(tmem + nh * 128, dAhi + ao, dBlo + bo, GEMM_IDESC, true);
                        mma_f16_ss(tmem + nh * 128, dAlo + ao, dBhi + bo, GEMM_IDESC, true);
                    }
                }
                TCGEN05_COMMIT(sbase + 8 + (kt & 1) * 8);
            }
        }

        // under cover of MMA(kt): free other buffer, refill it, wait landing
        if (kt + 1 < nkt) {
            if (kt > 0)
                MBARRIER_WAIT_PARITY(sbase + 8 + ((kt - 1) & 1) * 8, ((kt - 1) >> 1) & 1);
            gemm_fill(sbase + 1024 + ((kt + 1) & 1) * GB_SIZE, Ahi, Alo, Bhi, Blo,
                      rowBase, (kt + 1) * 64, t);
            CP_COMMIT();
            CP_WAIT(0);
            FENCE_PROXY_ASYNC();
            __syncthreads();
        }
    }
    // wait for the last MMA (in-order tensor queue => all earlier done too)
    MBARRIER_WAIT_PARITY(sbase + 8 + ((nkt - 1) & 1) * 8, ((nkt - 1) >> 1) & 1);
    TCGEN05_FENCE_AFTER();

    float* Ds = reinterpret_cast<float*>(smem + 1024);
#pragma unroll 1
    for (int qr = 0; qr < 4; qr++) {
        uint32_t d0[32], d1[32];
        TCGEN05_LD_32X32B_X32(d0, tmem + qr * 64);
        TCGEN05_LD_32X32B_X32(d1, tmem + qr * 64 + 32);
        TCGEN05_WAIT_LD();
        __syncthreads();
#pragma unroll
        for (int j = 0; j < 32; j++) Ds[t * 65 + j] = __uint_as_float(d0[j]);
#pragma unroll
        for (int j = 0; j < 32; j++) Ds[t * 65 + 32 + j] = __uint_as_float(d1[j]);
        __syncthreads();

        const int cw = rowInW + qr * 64;
        int out_sel; const float* bias;
        if (mode == 0) { out_sel = w; bias = (w == 0) ? b0 : (w == 1) ? b1 : b2; }
        else           { out_sel = 3; bias = b0; }

        if (out_sel == 2) {
            const int hdl = t >> 1, sh = t & 1;
            const float bv = __ldg(&bias[cw + hdl]);
            const int hh = cw >> 6;
            const size_t dstoff = ((size_t)(bb * HH + hh) * HDD + hdl) * SS
                                  + (rowBase & 2047) + sh * 64;
#pragma unroll
            for (int c = 0; c < 4; c++) {
                uint32_t hp[8], lp[8];
#pragma unroll
                for (int e = 0; e < 8; e++) {
                    float v0 = Ds[(sh * 64 + c * 16 + e * 2 + 0) * 65 + hdl] + bv;
                    float v1 = Ds[(sh * 64 + c * 16 + e * 2 + 1) * 65 + hdl] + bv;
                    float h0 = __bfloat162float(__float2bfloat16(v0));
                    float h1 = __bfloat162float(__float2bfloat16(v1));
                    hp[e] = pack_bf16x2(h0, h1);
                    lp[e] = pack_bf16x2(v0 - h0, v1 - h1);
                }
                *reinterpret_cast<uint4*>(g_vthi + dstoff + c * 16)     = *reinterpret_cast<uint4*>(hp);
                *reinterpret_cast<uint4*>(g_vthi + dstoff + c * 16 + 8) = *reinterpret_cast<uint4*>(hp + 4);
                *reinterpret_cast<uint4*>(g_vtlo + dstoff + c * 16)     = *reinterpret_cast<uint4*>(lp);
                *reinterpret_cast<uint4*>(g_vtlo + dstoff + c * 16 + 8) = *reinterpret_cast<uint4*>(lp + 4);
            }
        } else {
            float vals[64];
#pragma unroll
            for (int j = 0; j < 64; j++) vals[j] = Ds[t * 65 + j];
            epi_store(out_sel, cw >> 6, bb, ss, gRow, cw, vals, bias, Y);
        }
    }

    __syncthreads();
    if (t == 0) { MBARRIER_INVAL(sbase + 8); MBARRIER_INVAL(sbase + 16); }
    __syncthreads();
    if (wid == 0) TCGEN05_DEALLOC(tmem, 256);

#else  // FFMA fallback (non-'a' targets; never runs on GB300)
    float* As = reinterpret_cast<float*>(smem + 1024);
    float* Bs = As + 128 * 33;

#pragma unroll 1
    for (int qr = 0; qr < 4; qr++) {
        float acc[64];
#pragma unroll
        for (int j = 0; j < 64; j++) acc[j] = 0.0f;

        for (int kt = 0; kt < DD / 32; kt++) {
            const int k0 = kt * 32;
            __syncthreads();
#pragma unroll
            for (int k = 0; k < 32; k++) {
                size_t gi = (size_t)(rowBase + t) * DD + k0 + k;
                As[t * 33 + k] = __bfloat162float(Ahi[gi]) + __bfloat162float(Alo[gi]);
            }
#pragma unroll
            for (int i = 0; i < 16; i++) {
                int idx = t * 16 + i;
                int k = idx >> 6, j = idx & 63;
                size_t gi = (size_t)(rowInW + qr * 64 + j) * DD + k0 + k;
                Bs[k * 64 + j] = __bfloat162float(g_wthi[w][gi]) + __bfloat162float(g_wtlo[w][gi]);
            }
            __syncthreads();
#pragma unroll
            for (int k = 0; k < 32; k++) {
                float a = As[t * 33 + k];
#pragma unroll
                for (int j = 0; j < 64; j++) acc[j] += a * Bs[k * 64 + j];
            }
        }
        const int cw = rowInW + qr * 64;
        int out_sel; const float* bias;
        if (mode == 0) { out_sel = w; bias = (w == 0) ? b0 : (w == 1) ? b1 : b2; }
        else           { out_sel = 3; bias = b0; }
        epi_store(out_sel, cw >> 6, bb, ss, gRow, cw, acc, bias, Y);
        __syncthreads();
    }
#endif
}

// ------- tensor-core causal attention, SELECTIVE split-K ----------------
// (unchanged from R14: issuer warp 8, per-buffer mbarriers, STTM P,
//  last-finisher in-kernel combine for split rows)
#define AT_QHI  1024
#define AT_QLO  (1024 + 16384)
#define AT_K0   (1024 + 32768)   // K buf b at +b*16384 (hi +0, lo +8192)
#define AT_V0   (1024 + 65536)   // V buf b at +b*16384 (hi +0, lo +8192)
#define AT_TOTAL (1024 + 98304)  // 99328 -> 2 CTAs/SM

__global__ __launch_bounds__(288, 2) void tc_attn()
{
    extern __shared__ char smem[];
    const int t = threadIdx.x;
    const int qt = gridDim.x - 1 - blockIdx.x;   // longest CTAs first
    const int h = blockIdx.y;
    const int b = blockIdx.z >> 1, sp = blockIdx.z & 1;
    const bool split = (qt >= SPLIT_QT);
    if (!split && sp == 1) return;               // empty CTA
    const size_t bh = (size_t)(b * HH + h);

    const int n = split ? (qt + 1) : (2 * qt + 2);
    const int ktBeg = split ? sp * n : 0;

#if HAS_TC
    const uint32_t sbase = smem_u32(smem);
    const int wid = t >> 5;          // 0..8
    const int lid = t & 31;
    const bool smx = (wid < 8);
    const int sub = wid & 3;
    const int ch  = wid >> 2;
    const int row = sub * 32 + lid;
    const int qi = qt * 128 + row;
    const uint32_t mbarS0 = sbase + 8;
    const uint32_t mbarS1 = sbase + 16;
    const uint32_t mbarP  = sbase + 24;
    const uint32_t warp_off = ((uint32_t)sub) << 21;

    if (wid == 0) { TCGEN05_ALLOC(sbase, 256); TCGEN05_RELINQUISH(); }
    if (t == 0) { MBARRIER_INIT(mbarS0, 1); MBARRIER_INIT(mbarS1, 1); MBARRIER_INIT(mbarP, 1); }
    __syncthreads();
    uint32_t tmem;
    asm volatile("ld.shared.b32 %0, [%1];" : "=r"(tmem) : "r"(sbase));
    const uint32_t tS0 = tmem;
    const uint32_t tS1 = tmem + 64;
    const uint32_t tO  = tmem + 128;
    const uint32_t tPH = tmem + 192;
    const uint32_t tPL = tmem + 224;

    // ---- prologue: Q tile + K/V(ktBeg) ----
    if (smx) {
        const uint4* qh = reinterpret_cast<const uint4*>(g_qhi + (bh * SS + (size_t)qt * 128) * HDD);
        const uint4* ql = reinterpret_cast<const uint4*>(g_qlo + (bh * SS + (size_t)qt * 128) * HDD);
#pragma unroll
        for (int i = 0; i < 4; i++) {
            int idx = i * 256 + t;
            int r = idx >> 3, slot = idx & 7;
            uint32_t off = SWZ128((uint32_t)(r * 128 + slot * 16));
            *reinterpret_cast<uint4*>(smem + AT_QHI + off) = qh[idx];
            *reinterpret_cast<uint4*>(smem + AT_QLO + off) = ql[idx];
        }
        const int kb0 = ktBeg * 64;
        const uint4* kh = reinterpret_cast<const uint4*>(g_khi + (bh * SS + kb0) * HDD);
        const uint4* kl = reinterpret_cast<const uint4*>(g_klo + (bh * SS + kb0) * HDD);
#pragma unroll
        for (int i = 0; i < 2; i++) {
            int idx = i * 256 + t;
            int r = idx >> 3, slot = idx & 7;
            uint32_t off = SWZ128((uint32_t)(r * 128 + slot * 16));
            *reinterpret_cast<uint4*>(smem + AT_K0 + off) = kh[idx];
            *reinterpret_cast<uint4*>(smem + AT_K0 + 8192 + off) = kl[idx];
            *reinterpret_cast<uint4*>(smem + AT_V0 + off) =
                reinterpret_cast<const uint4*>(g_vthi + (bh * HDD + r) * SS + kb0)[slot];
            *reinterpret_cast<uint4*>(smem + AT_V0 + 8192 + off) =
                reinterpret_cast<const uint4*>(g_vtlo + (bh * HDD + r) * SS + kb0)[slot];
        }
        FENCE_PROXY_ASYNC();
    }
    __syncthreads();

    const uint64_t dQhi = MAKE_SMEM_DESC(sbase + AT_QHI);
    const uint64_t dQlo = MAKE_SMEM_DESC(sbase + AT_QLO);

    // prologue: issue S(i=0) -> tS0
    if (wid == 8) {
        if (elect_one_pred()) {
            const uint64_t dKhi = MAKE_SMEM_DESC(sbase + AT_K0);
            const uint64_t dKlo = MAKE_SMEM_DESC(sbase + AT_K0 + 8192);
#pragma unroll
            for (int ks = 0; ks < 4; ks++) {
                const uint64_t off = ks * 2;
                mma_f16_ss(tS0, dQhi + off, dKhi + off, ATT_IDESC, ks != 0);
                mma_f16_ss(tS0, dQhi + off, dKlo + off, ATT_IDESC, true);
                mma_f16_ss(tS0, dQlo + off, dKhi + off, ATT_IDESC, true);
            }
            TCGEN05_COMMIT(mbarS0);
        }
    }

    float lpart = 0.0f;
    int phP = 0;

    for (int i = 0; i < n; i++) {
        const int kt = ktBeg + i;
        const bool pre = (i + 1 < n);
        uint4 pvh[2], pvl[2];

        // --- load warps: store K(i+1), prefetch V(i+1) ---
        if (smx && pre) {
            const int nb = (kt + 1) * 64;
            const uint32_t kb = AT_K0 + ((i + 1) & 1) * 16384;
            const uint4* kh = reinterpret_cast<const uint4*>(g_khi + (bh * SS + nb) * HDD);
            const uint4* kl = reinterpret_cast<const uint4*>(g_klo + (bh * SS + nb) * HDD);
#pragma unroll
            for (int j = 0; j < 2; j++) {
                int idx = j * 256 + t;
                int r = idx >> 3, slot = idx & 7;
                uint32_t off = SWZ128((uint32_t)(r * 128 + slot * 16));
                *reinterpret_cast<uint4*>(smem + kb + off) = kh[idx];
                *reinterpret_cast<uint4*>(smem + kb + 8192 + off) = kl[idx];
                pvh[j] = reinterpret_cast<const uint4*>(g_vthi + (bh * HDD + r) * SS + nb)[slot];
                pvl[j] = reinterpret_cast<const uint4*>(g_vtlo + (bh * HDD + r) * SS + nb)[slot];
            }
            FENCE_PROXY_ASYNC();
        }
        __syncthreads();   // the ONLY sync per iteration

        if (wid == 8) {
            // ---- issuer warp: PV(i-1) first, then S(i+1) ----
            if (elect_one_pred()) {
                TCGEN05_FENCE_AFTER();
                if (i > 0) {
                    const uint32_t vb = sbase + AT_V0 + ((i - 1) & 1) * 16384;
                    const uint64_t dVhi = MAKE_SMEM_DESC(vb);
                    const uint64_t dVlo = MAKE_SMEM_DESC(vb + 8192);
#pragma unroll
                    for (int ks = 0; ks < 4; ks++) {
                        const uint64_t off = ks * 2;
                        const bool first = (i == 1) && (ks == 0);
                        mma_f16_ts(tO, tPH + ks * 8, dVhi + off, ATT_IDESC, !first);
                        mma_f16_ts(tO, tPH + ks * 8, dVlo + off, ATT_IDESC, true);
                        mma_f16_ts(tO, tPL + ks * 8, dVhi + off, ATT_IDESC, true);
                    }
                    TCGEN05_COMMIT(mbarP);
                }
                if (pre) {
                    const uint32_t kb = sbase + AT_K0 + ((i + 1) & 1) * 16384;
                    const uint64_t dKhi = MAKE_SMEM_DESC(kb);
                    const uint64_t dKlo = MAKE_SMEM_DESC(kb + 8192);
                    const uint32_t tSn = ((i + 1) & 1) ? tS1 : tS0;
#pragma unroll
                    for (int ks = 0; ks < 4; ks++) {
                        const uint64_t off = ks * 2;
                        mma_f16_ss(tSn, dQhi + off, dKhi + off, ATT_IDESC, ks != 0);
                        mma_f16_ss(tSn, dQhi + off, dKlo + off, ATT_IDESC, true);
                        mma_f16_ss(tSn, dQlo + off, dKhi + off, ATT_IDESC, true);
                    }
                    TCGEN05_COMMIT(((i + 1) & 1) ? mbarS1 : mbarS0);
                }
            }
        } else {
            // ---- softmax warps ----
            MBARRIER_WAIT_PARITY((i & 1) ? mbarS1 : mbarS0, (i >> 1) & 1);
            TCGEN05_FENCE_AFTER();

            float s_[32];
            {
                const uint32_t tSc = ((i & 1) ? tS1 : tS0) + ch * 32;
                TCGEN05_LD_32X32B_X32(reinterpret_cast<uint32_t*>(s_), tSc);
            }
            TCGEN05_WAIT_LD();

            const int cb0 = kt * 64 + ch * 32;
            if (kt >= 2 * qt) {
#pragma unroll
                for (int j = 0; j < 32; j++)
                    if (cb0 + j > qi) s_[j] = -1e30f;
            }
            float sum = 0.0f;
#pragma unroll
            for (int j = 0; j < 32; j++) {
                float e = (j % 3 == 0) ? exp2_poly(s_[j]) : ex2_mufu(s_[j]);
                s_[j] = e;
                sum += e;
            }
            lpart += sum;

            if (i > 0) { MBARRIER_WAIT_PARITY(mbarP, phP & 1); phP++; }

            // split P -> bf16 hi/lo straight into TMEM
            {
                uint32_t hw[16], lw[16];
#pragma unroll
                for (int g = 0; g < 16; g++) {
                    float p0 = s_[g*2+0], p1 = s_[g*2+1];
                    float h0 = __bfloat162float(__float2bfloat16(p0));
                    float h1 = __bfloat162float(__float2bfloat16(p1));
                    hw[g] = pack_bf16x2(h0, h1);
                    lw[g] = pack_bf16x2(p0 - h0, p1 - h1);
                }
                TCGEN05_ST_32X32B_X16(tPH + ch * 16 + warp_off, hw);
                TCGEN05_ST_32X32B_X16(tPL + ch * 16 + warp_off, lw);
                TCGEN05_WAIT_ST();
            }
            TCGEN05_FENCE_BEFORE();

            // store V(i+1) (buffer free: PV(i-1) waited above)
            if (pre) {
                const uint32_t vb = AT_V0 + ((i + 1) & 1) * 16384;
#pragma unroll
                for (int j = 0; j < 2; j++) {
                    int idx = j * 256 + t;
                    int r = idx >> 3, slot = idx & 7;
                    uint32_t off = SWZ128((uint32_t)(r * 128 + slot * 16));
                    *reinterpret_cast<uint4*>(smem + vb + off) = pvh[j];
                    *reinterpret_cast<uint4*>(smem + vb + 8192 + off) = pvl[j];
                }
                FENCE_PROXY_ASYNC();
            }
        }
    }

    // ---- tail: issue final PV(n-1) ----
    __syncthreads();
    if (wid == 8) {
        if (elect_one_pred()) {
            TCGEN05_FENCE_AFTER();
            const uint32_t vb = sbase + AT_V0 + ((n - 1) & 1) * 16384;
            const uint64_t dVhi = MAKE_SMEM_DESC(vb);
            const uint64_t dVlo = MAKE_SMEM_DESC(vb + 8192);
#pragma unroll
            for (int ks = 0; ks < 4; ks++) {
                const uint64_t off = ks * 2;
                const bool first = (n == 1) && (ks == 0);
                mma_f16_ts(tO, tPH + ks * 8, dVhi + off, ATT_IDESC, !first);
                mma_f16_ts(tO, tPH + ks * 8, dVlo + off, ATT_IDESC, true);
                mma_f16_ts(tO, tPL + ks * 8, dVhi + off, ATT_IDESC, true);
            }
            TCGEN05_COMMIT(mbarP);
        }
    }

    MBARRIER_WAIT_PARITY(mbarP, (n - 1) & 1);
    TCGEN05_FENCE_AFTER();

    // ---- epilogue ----
    if (smx) {
        float* sums = reinterpret_cast<float*>(smem + AT_QHI);
        sums[ch * 128 + row] = lpart;
    }
    __syncthreads();

    if (smx) {
        float O[32];
        TCGEN05_LD_32X32B_X32(reinterpret_cast<uint32_t*>(O), tO + ch * 32);
        TCGEN05_WAIT_LD();

        const float* sums = reinterpret_cast<const float*>(smem + AT_QHI);
        const float ltot = sums[row] + sums[128 + row];

        if (split) {
            const size_t prow = bh * SS + qi;
            if (ch == 0) g_lp[sp][prow] = ltot;
            float* dst = g_po + ((size_t)sp * NROWS_ATT + prow) * HDD + ch * 32;
#pragma unroll
            for (int g = 0; g < 8; g++)
                *reinterpret_cast<float4*>(dst + g * 4) = *reinterpret_cast<float4*>(O + g * 4);
        } else {
            const float inv = 1.0f / ltot;
            size_t ob = ((size_t)b * SS + qi) * DD + h * HDD + ch * 32;
#pragma unroll
            for (int g = 0; g < 4; g++) {
                uint32_t hw[4], lw[4];
#pragma unroll
                for (int e2 = 0; e2 < 4; e2++) {
                    float v0 = O[g*8 + e2*2+0] * inv;
                    float v1 = O[g*8 + e2*2+1] * inv;
                    float h0 = __bfloat162float(__float2bfloat16(v0));
                    float h1 = __bfloat162float(__float2bfloat16(v1));
                    hw[e2] = pack_bf16x2(h0, h1);
                    lw[e2] = pack_bf16x2(v0 - h0, v1 - h1);
                }
                *reinterpret_cast<uint4*>(g_chi + ob + g*8) = *reinterpret_cast<uint4*>(hw);
                *reinterpret_cast<uint4*>(g_clo + ob + g*8) = *reinterpret_cast<uint4*>(lw);
            }
        }
    }

    // ---- last-finisher combine (split rows only) ----
    if (split) {
        __threadfence();
        __syncthreads();
        int* sflag = reinterpret_cast<int*>(smem + 32);
        if (t == 0) {
            const int fidx = (int)bh * (16 - SPLIT_QT) + (qt - SPLIT_QT);
            *sflag = atomicAdd(&g_flag[fidx], 1);
        }
        __syncthreads();
        if (*sflag == 1 && smx) {
            const size_t prow = bh * SS + qi;
            const float inv = 1.0f / (g_lp[0][prow] + g_lp[1][prow]);
            const float4* p0 = reinterpret_cast<const float4*>(g_po + prow * HDD + ch * 32);
            const float4* p1 = reinterpret_cast<const float4*>(
                g_po + ((size_t)NROWS_ATT + prow) * HDD + ch * 32);
            size_t ob = ((size_t)b * SS + qi) * DD + h * HDD + ch * 32;
#pragma unroll
            for (int g = 0; g < 4; g++) {
                float4 a0 = p0[g*2+0], a1 = p0[g*2+1];
                float4 c0 = p1[g*2+0], c1 = p1[g*2+1];
                float v[8];
                v[0] = (a0.x + c0.x) * inv; v[1] = (a0.y + c0.y) * inv;
                v[2] = (a0.z + c0.z) * inv; v[3] = (a0.w + c0.w) * inv;
                v[4] = (a1.x + c1.x) * inv; v[5] = (a1.y + c1.y) * inv;
                v[6] = (a1.z + c1.z) * inv; v[7] = (a1.w + c1.w) * inv;
                uint32_t hw[4], lw[4];
#pragma unroll
                for (int e = 0; e < 4; e++) {
                    float h0 = __bfloat162float(__float2bfloat16(v[e*2+0]));
                    float h1 = __bfloat162float(__float2bfloat16(v[e*2+1]));
                    hw[e] = pack_bf16x2(h0, h1);
                    lw[e] = pack_bf16x2(v[e*2+0] - h0, v[e*2+1] - h1);
                }
                *reinterpret_cast<uint4*>(g_chi + ob + g*8) = *reinterpret_cast<uint4*>(hw);
                *reinterpret_cast<uint4*>(g_clo + ob + g*8) = *reinterpret_cast<uint4*>(lw);
            }
        }
    }

    __syncthreads();
    if (t == 0) { MBARRIER_INVAL(mbarS0); MBARRIER_INVAL(mbarS1); MBARRIER_INVAL(mbarP); }
    __syncthreads();
    if (wid == 0) TCGEN05_DEALLOC(tmem, 256);

#else  // scalar fallback (never runs on GB300)
    __shared__ int sflag2;
    if (t < 128) {
        const int qi2 = qt * 128 + t;
        float q[64];
#pragma unroll
        for (int d = 0; d < 64; d++) {
            size_t o = (bh * SS + qi2) * HDD + d;
            q[d] = __bfloat162float(g_qhi[o]) + __bfloat162float(g_qlo[o]);
        }
        float O[64];
#pragma unroll
        for (int d = 0; d < 64; d++) O[d] = 0.0f;
        float l = 0.0f;
        const int kLo = ktBeg * 64;
        const int kHi = (ktBeg + n) * 64 - 1;
        const int kEnd = (qi2 < kHi) ? qi2 : kHi;
        for (int k = kLo; k <= kEnd; k++) {
            float s = 0.0f;
            size_t kb = (bh * SS + k) * HDD;
            for (int d = 0; d < 64; d++)
                s += q[d] * (__bfloat162float(g_khi[kb + d]) + __bfloat162float(g_klo[kb + d]));
            float p = exp2f(s);
            l += p;
            for (int d = 0; d < 64; d++) {
                size_t vo = (bh * HDD + d) * SS + k;
                O[d] += p * (__bfloat162float(g_vthi[vo]) + __bfloat162float(g_vtlo[vo]));
            }
        }
        if (split) {
            const size_t prow = bh * SS + qi2;
            g_lp[sp][prow] = l;
            float* dst = g_po + ((size_t)sp * NROWS_ATT + prow) * HDD;
            for (int d = 0; d < 64; d++) dst[d] = O[d];
        } else {
            const float inv = 1.0f / l;
            size_t ob = ((size_t)b * SS + qi2) * DD + h * HDD;
            for (int d = 0; d < 64; d++) {
                float v = O[d] * inv;
                __nv_bfloat16 hb = __float2bfloat16(v);
                g_chi[ob + d] = hb;
                g_clo[ob + d] = __float2bfloat16(v - __bfloat162float(hb));
            }
        }
    }
    if (split) {
        __threadfence();
        __syncthreads();
        if (t == 0) {
            const int fidx = (int)bh * (16 - SPLIT_QT) + (qt - SPLIT_QT);
            sflag2 = atomicAdd(&g_flag[fidx], 1);
        }
        __syncthreads();
        if (sflag2 == 1 && t < 128) {
            const int qi2 = qt * 128 + t;
            const size_t prow = bh * SS + qi2;
            const float inv = 1.0f / (g_lp[0][prow] + g_lp[1][prow]);
            size_t ob = ((size_t)b * SS + qi2) * DD + h * HDD;
            for (int d = 0; d < 64; d++) {
                float v = (g_po[prow * HDD + d] + g_po[(size_t)NROWS_ATT * HDD + prow * HDD + d]) * inv;
                __nv_bfloat16 hb = __float2bfloat16(v);
                g_chi[ob + d] = hb;
                g_clo[ob + d] = __float2bfloat16(v - __bfloat162float(hb));
            }
        }
    }
#endif
}

// ---------------------------------------------------------------------------
extern "C" void kernel_launch(void* const* d_in, const int* in_sizes, int n_in,
                              void* d_out, int out_size)
{
    const float* x  = (const float*)d_in[0];
    const float* wq = (const float*)d_in[1];
    const float* bq = (const float*)d_in[2];
    const float* wk = (const float*)d_in[3];
    const float* bk = (const float*)d_in[4];
    const float* wv = (const float*)d_in[5];
    const float* bv = (const float*)d_in[6];
    const float* wo = (const float*)d_in[7];
    const float* bo = (const float*)d_in[8];
    float* out = (float*)d_out;

    cudaFuncSetAttribute(tc_gemm, cudaFuncAttributeMaxDynamicSharedMemorySize, GM_TOTAL);
    cudaFuncSetAttribute(tc_attn, cudaFuncAttributeMaxDynamicSharedMemorySize, AT_TOTAL);

    // fused prep: weight transpose+split (2304 blocks) + x split (6144 blocks)
    prep_kernel<<<8448, 256>>>(x, wq, wk, wv, wo);

    // fused QKV: N = 2304 -> 9 col-blocks of 256
    tc_gemm<<<dim3(9, MROWS / 128), 128, GM_TOTAL>>>(bq, bk, bv, nullptr, 0, 0);

    // selective split-K attention with in-kernel last-finisher combine
    tc_attn<<<dim3(SS / 128, HH, BB * 2), 288, AT_TOTAL>>>();

    // O-projection: N = 768 -> 3 col-blocks of 256
    tc_gemm<<<dim3(3, MROWS / 128), 128, GM_TOTAL>>>(bo, bo, bo, out, 1, 1);
}

// round 17
// speedup vs baseline: 1.0883x; 1.0851x over previous
#include <cuda_runtime.h>
#include <cuda_bf16.h>
#include <cstdint>

#define BB 2
#define SS 2048
#define DD 768
#define HH 12
#define HDD 64
#define MROWS (BB*SS)   // 4096
#define NROWS_ATT (BB*HH*SS)   // 49152
#define SPLIT_QT 8      // split key range for qt >= SPLIT_QT

#if defined(__CUDA_ARCH__) && \
    ((__CUDA_ARCH__ == 1030 && defined(__CUDA_ARCH_FEAT_SM103_ALL)) || \
     (__CUDA_ARCH__ == 1000 && defined(__CUDA_ARCH_FEAT_SM100_ALL)) || \
     (__CUDA_ARCH__ == 1010 && defined(__CUDA_ARCH_FEAT_SM101_ALL)))
#define HAS_TC 1
#else
#define HAS_TC 0
#endif

// log2(e) folded into Q so softmax uses exp2
#define QSCALE 0.18033688011112042f   // 0.125 * log2(e)

// ---------------- device scratch (allocation-free rule) ----------------
__device__ __nv_bfloat16 g_xhi[MROWS*DD], g_xlo[MROWS*DD];
__device__ __nv_bfloat16 g_chi[MROWS*DD], g_clo[MROWS*DD];
__device__ __nv_bfloat16 g_wthi[4][DD*DD], g_wtlo[4][DD*DD];   // [N][K]
__device__ __nv_bfloat16 g_qhi[BB*HH*SS*HDD], g_qlo[BB*HH*SS*HDD];
__device__ __nv_bfloat16 g_khi[BB*HH*SS*HDD], g_klo[BB*HH*SS*HDD];
__device__ __nv_bfloat16 g_vthi[BB*HH*SS*HDD], g_vtlo[BB*HH*SS*HDD];
// split-K attention partials (only qt >= SPLIT_QT rows)
__device__ float g_po[2ull*NROWS_ATT*HDD];
__device__ float g_lp[2][NROWS_ATT];
__device__ int   g_flag[BB*HH*(16 - SPLIT_QT)];   // 192 finisher flags

// ---------------- PTX helpers ------------------------------------------
__device__ __forceinline__ uint32_t smem_u32(const void* p) {
    uint32_t a;
    asm("{ .reg .u64 t; cvta.to.shared.u64 t, %1; cvt.u32.u64 %0, t; }" : "=r"(a) : "l"(p));
    return a;
}
__device__ __forceinline__ float ex2_mufu(float x) {
    float r; asm("ex2.approx.f32 %0, %1;" : "=f"(r) : "f"(x)); return r;
}
// exp2 via FMA pipe: magic-constant floor + degree-4 poly on [-0.5, 0.5]
__device__ __forceinline__ float exp2_poly(float y) {
    y = fmaxf(y, -125.0f);
    float z = y + 12582912.0f;
    float f = y - (z - 12582912.0f);
    int   n = __float_as_int(z) - 0x4B400000;
    float p = 0.0096181291f;
    p = fmaf(p, f, 0.0555041087f);
    p = fmaf(p, f, 0.2402265069f);
    p = fmaf(p, f, 0.6931471806f);
    p = fmaf(p, f, 1.0f);
    return __int_as_float(__float_as_int(p) + (n << 23));
}

#if HAS_TC
__device__ __forceinline__ uint32_t elect_one_pred() {
    uint32_t pred;
    asm volatile(
        "{\n\t.reg .pred p;\n\telect.sync _|p, 0xFFFFFFFF;\n\tselp.b32 %0, 1, 0, p;\n\t}"
        : "=r"(pred));
    return pred;
}

#define TCGEN05_ALLOC(smem_result_addr, nCols) \
    asm volatile("tcgen05.alloc.cta_group::1.sync.aligned.shared::cta.b32 [%0], %1;" \
                 :: "r"((uint32_t)(smem_result_addr)), "r"((uint32_t)(nCols)) : "memory")
#define TCGEN05_DEALLOC(tmem_addr, nCols) \
    asm volatile("tcgen05.dealloc.cta_group::1.sync.aligned.b32 %0, %1;" \
                 :: "r"(tmem_addr), "r"((uint32_t)(nCols)))
#define TCGEN05_RELINQUISH() \
    asm volatile("tcgen05.relinquish_alloc_permit.cta_group::1.sync.aligned;")
#define TCGEN05_COMMIT(mbar) \
    asm volatile("tcgen05.commit.cta_group::1.mbarrier::arrive::one.shared::cluster.b64 [%0];" \
                 :: "r"((uint32_t)(mbar)) : "memory")
#define TCGEN05_WAIT_LD() asm volatile("tcgen05.wait::ld.sync.aligned;" ::: "memory")
#define TCGEN05_WAIT_ST() asm volatile("tcgen05.wait::st.sync.aligned;" ::: "memory")
#define TCGEN05_FENCE_AFTER() asm volatile("tcgen05.fence::after_thread_sync;" ::: "memory")
#define TCGEN05_FENCE_BEFORE() asm volatile("tcgen05.fence::before_thread_sync;" ::: "memory")
#define FENCE_PROXY_ASYNC() asm volatile("fence.proxy.async.shared::cta;" ::: "memory")

#define MBARRIER_INIT(mbar, count) \
    asm volatile("mbarrier.init.shared.b64 [%0], %1;" \
                 :: "r"((uint32_t)(mbar)), "r"((uint32_t)(count)) : "memory")
#define MBARRIER_INVAL(mbar) \
    asm volatile("mbarrier.inval.shared.b64 [%0];" :: "r"((uint32_t)(mbar)) : "memory")

#define MBARRIER_WAIT_PARITY(mbar_smem_addr, phase_parity) do { \
    uint32_t _mbar = (uint32_t)(mbar_smem_addr); \
    uint32_t _parity = (uint32_t)(phase_parity); \
    uint32_t _done; \
    asm volatile( \
        "{\n\t.reg .pred p;\n\t" \
        "mbarrier.try_wait.parity.acquire.cta.shared::cta.b64 p, [%1], %2;\n\t" \
        "selp.b32 %0, 1, 0, p;\n\t}" \
        : "=r"(_done) : "r"(_mbar), "r"(_parity) : "memory"); \
    if (!_done) { \
        asm volatile( \
            "{\n\t.reg .pred P1;\n\t" \
            "WAIT_LOOP_%=:\n\t" \
            "mbarrier.try_wait.parity.acquire.cta.shared::cta.b64 P1, [%0], %1, 0x989680;\n\t" \
            "@P1 bra.uni WAIT_DONE_%=;\n\t" \
            "bra.uni WAIT_LOOP_%=;\n\t" \
            "WAIT_DONE_%=:\n\t}" \
            :: "r"(_mbar), "r"(_parity) : "memory"); \
    } \
} while(0)

#define TCGEN05_LD_32X32B_X32(r, tmem_addr) \
    asm volatile( \
        "tcgen05.ld.sync.aligned.32x32b.x32.b32 " \
        "{%0, %1, %2, %3, %4, %5, %6, %7, " \
        " %8, %9, %10, %11, %12, %13, %14, %15, " \
        " %16, %17, %18, %19, %20, %21, %22, %23, " \
        " %24, %25, %26, %27, %28, %29, %30, %31}, [%32];" \
        : "=r"((r)[0]),  "=r"((r)[1]),  "=r"((r)[2]),  "=r"((r)[3]), \
          "=r"((r)[4]),  "=r"((r)[5]),  "=r"((r)[6]),  "=r"((r)[7]), \
          "=r"((r)[8]),  "=r"((r)[9]),  "=r"((r)[10]), "=r"((r)[11]), \
          "=r"((r)[12]), "=r"((r)[13]), "=r"((r)[14]), "=r"((r)[15]), \
          "=r"((r)[16]), "=r"((r)[17]), "=r"((r)[18]), "=r"((r)[19]), \
          "=r"((r)[20]), "=r"((r)[21]), "=r"((r)[22]), "=r"((r)[23]), \
          "=r"((r)[24]), "=r"((r)[25]), "=r"((r)[26]), "=r"((r)[27]), \
          "=r"((r)[28]), "=r"((r)[29]), "=r"((r)[30]), "=r"((r)[31]) \
        : "r"(tmem_addr))

#define TCGEN05_ST_32X32B_X16(tmem_addr, r) \
    asm volatile( \
        "tcgen05.st.sync.aligned.32x32b.x16.b32 [%0], " \
        "{%1, %2, %3, %4, %5, %6, %7, %8, " \
        " %9, %10, %11, %12, %13, %14, %15, %16};" \
        :: "r"(tmem_addr), \
           "r"((r)[0]),  "r"((r)[1]),  "r"((r)[2]),  "r"((r)[3]), \
           "r"((r)[4]),  "r"((r)[5]),  "r"((r)[6]),  "r"((r)[7]), \
           "r"((r)[8]),  "r"((r)[9]),  "r"((r)[10]), "r"((r)[11]), \
           "r"((r)[12]), "r"((r)[13]), "r"((r)[14]), "r"((r)[15]) \
        : "memory")

#define CP_ASYNC16(dst, src) \
    asm volatile("cp.async.cg.shared.global [%0], [%1], 16;" :: "r"(dst), "l"(src) : "memory")
#define CP_COMMIT() asm volatile("cp.async.commit_group;" ::: "memory")
#define CP_WAIT(n)  asm volatile("cp.async.wait_group %0;" :: "n"(n) : "memory")

__device__ __forceinline__ void mma_f16_ss(uint32_t d_tmem, uint64_t a_desc, uint64_t b_desc,
                                           uint32_t idesc, bool acc) {
    uint32_t en = acc ? 1u : 0u;
    uint32_t zero = 0u;
    asm volatile(
        "{\n\t.reg .pred p;\n\t"
        "setp.ne.u32 p, %5, 0;\n\t"
        "tcgen05.mma.cta_group::1.kind::f16 [%0], %1, %2, %3, {%4, %4, %4, %4}, p;\n\t}"
        :: "r"(d_tmem), "l"(a_desc), "l"(b_desc), "r"(idesc), "r"(zero), "r"(en)
        : "memory");
}

// TS form: A in TMEM
__device__ __forceinline__ void mma_f16_ts(uint32_t d_tmem, uint32_t a_tmem, uint64_t b_desc,
                                           uint32_t idesc, bool acc) {
    uint32_t en = acc ? 1u : 0u;
    uint32_t zero = 0u;
    asm volatile(
        "{\n\t.reg .pred p;\n\t"
        "setp.ne.u32 p, %5, 0;\n\t"
        "tcgen05.mma.cta_group::1.kind::f16 [%0], [%1], %2, %3, {%4, %4, %4, %4}, p;\n\t}"
        :: "r"(d_tmem), "r"(a_tmem), "l"(b_desc), "r"(idesc), "r"(zero), "r"(en)
        : "memory");
}
#endif  // HAS_TC

// SW128 (128B rows)
static constexpr uint64_t SMEM_DESC_BASE_SW128 =
    (uint64_t(2) << 61) | (uint64_t(1) << 46) | (uint64_t(64) << 32) | (uint64_t(1) << 16);
#define MAKE_SMEM_DESC(addr) (SMEM_DESC_BASE_SW128 | ((uint64_t)((addr) >> 4) & 0x3FFF))
#define SWZ128(off) ((off) ^ (((off) >> 3) & 0x70))

static constexpr uint32_t GEMM_IDESC =            // M=128, N=128
    (1u << 4) | (1u << 7) | (1u << 10) | (16u << 17) | (8u << 24);
static constexpr uint32_t ATT_IDESC =             // M=128, N=64
    (1u << 4) | (1u << 7) | (1u << 10) | (8u << 17) | (8u << 24);

__device__ __forceinline__ uint32_t pack_bf16x2(float a, float b) {
    __nv_bfloat162 t2 = __floats2bfloat162_rn(a, b);
    return *reinterpret_cast<uint32_t*>(&t2);
}

// -------- fused prep: weight transpose+split, x split, flag zero --------
__global__ void prep_kernel(const float* __restrict__ x,
                            const float* __restrict__ w0, const float* __restrict__ w1,
                            const float* __restrict__ w2, const float* __restrict__ w3)
{
    __shared__ float tile[32][33];
    const int bx = blockIdx.x;
    const int tid = threadIdx.x;
    if (bx == 0 && tid < BB*HH*(16 - SPLIT_QT)) g_flag[tid] = 0;

    if (bx < 2304) {
        const int widx = bx / 576;
        const int r = bx - widx * 576;
        const int n0 = (r % 24) * 32, k0 = (r / 24) * 32;
        const float* src = (widx == 0) ? w0 : (widx == 1) ? w1 : (widx == 2) ? w2 : w3;
        const int tx = tid & 31, ty = tid >> 5;   // (32, 8)
#pragma unroll
        for (int rr = 0; rr < 4; rr++)
            tile[ty + rr * 8][tx] = src[(k0 + ty + rr * 8) * DD + n0 + tx];
        __syncthreads();
        __nv_bfloat16* hiT = g_wthi[widx];
        __nv_bfloat16* loT = g_wtlo[widx];
#pragma unroll
        for (int rr = 0; rr < 4; rr++) {
            float v = tile[tx][ty + rr * 8];
            __nv_bfloat16 h = __float2bfloat16(v);
            int o = (n0 + ty + rr * 8) * DD + k0 + tx;
            hiT[o] = h;
            loT[o] = __float2bfloat16(v - __bfloat162float(h));
        }
    } else {
        const int i = (bx - 2304) * 256 + tid;
        float2 v = reinterpret_cast<const float2*>(x)[i];
        __nv_bfloat16 h0 = __float2bfloat16(v.x);
        __nv_bfloat16 h1 = __float2bfloat16(v.y);
        __nv_bfloat162 hp; hp.x = h0; hp.y = h1;
        __nv_bfloat162 lp;
        lp.x = __float2bfloat16(v.x - __bfloat162float(h0));
        lp.y = __float2bfloat16(v.y - __bfloat162float(h1));
        reinterpret_cast<__nv_bfloat162*>(g_xhi)[i] = hp;
        reinterpret_cast<__nv_bfloat162*>(g_xlo)[i] = lp;
    }
}

// ---------------- shared epilogue writer (Q/K/Y paths) ------------------
__device__ __forceinline__ void epi_store(int out_sel, int hh, int bb, int ss, int gRow,
                                          int cw, const float* vals,
                                          const float* __restrict__ bias, float* Y)
{
    if (out_sel == 3) {
        float* dst = Y + (size_t)gRow * DD + cw;
#pragma unroll
        for (int g = 0; g < 16; g++) {
            float4 o;
            o.x = vals[g*4+0] + __ldg(&bias[cw + g*4+0]);
            o.y = vals[g*4+1] + __ldg(&bias[cw + g*4+1]);
            o.z = vals[g*4+2] + __ldg(&bias[cw + g*4+2]);
            o.w = vals[g*4+3] + __ldg(&bias[cw + g*4+3]);
            *reinterpret_cast<float4*>(dst + g*4) = o;
        }
    } else if (out_sel <= 1) {
        __nv_bfloat16* Hi = out_sel ? g_khi : g_qhi;
        __nv_bfloat16* Lo = out_sel ? g_klo : g_qlo;
        const float sc = out_sel ? 1.0f : QSCALE;
        size_t ob = ((size_t)(bb * HH + hh) * SS + ss) * HDD;
#pragma unroll
        for (int g = 0; g < 8; g++) {
            uint32_t hw[4], lw[4];
#pragma unroll
            for (int e2 = 0; e2 < 4; e2++) {
                float v0 = (vals[g*8 + e2*2+0] + __ldg(&bias[cw + g*8 + e2*2+0])) * sc;
                float v1 = (vals[g*8 + e2*2+1] + __ldg(&bias[cw + g*8 + e2*2+1])) * sc;
                float h0 = __bfloat162float(__float2bfloat16(v0));
                float h1 = __bfloat162float(__float2bfloat16(v1));
                hw[e2] = pack_bf16x2(h0, h1);
                lw[e2] = pack_bf16x2(v0 - h0, v1 - h1);
            }
            *reinterpret_cast<uint4*>(Hi + ob + g*8) = *reinterpret_cast<uint4*>(hw);
            *reinterpret_cast<uint4*>(Lo + ob + g*8) = *reinterpret_cast<uint4*>(lw);
        }
    } else {
        size_t vb = (size_t)(bb * HH + hh) * HDD;
#pragma unroll
        for (int j = 0; j < 64; j++) {
            float v = vals[j] + __ldg(&bias[cw + j]);
            __nv_bfloat16 hb = __float2bfloat16(v);
            size_t o = (vb + j) * SS + ss;
            g_vthi[o] = hb;
            g_vtlo[o] = __float2bfloat16(v - __bfloat162float(hb));
        }
    }
}

// ---- GEMM: CTA 128x256, k-tile 64 (SW128), R14 loop (measured best) ----
// Descriptors for both buffers hoisted out of the mainloop.
#define GB_AHI 0
#define GB_ALO 16384
#define GB_BHI 32768
#define GB_BLO 65536
#define GB_SIZE 98304
#define GM_TOTAL (1024 + 2*GB_SIZE)   // 197632

#if HAS_TC
__device__ __forceinline__ void gemm_fill(uint32_t buf,
                                          const __nv_bfloat16* __restrict__ Ahi,
                                          const __nv_bfloat16* __restrict__ Alo,
                                          const __nv_bfloat16* __restrict__ Bhi,
                                          const __nv_bfloat16* __restrict__ Blo,
                                          int rowBase, int k0, int t)
{
#pragma unroll
    for (int i = 0; i < 8; i++) {          // A: 128 rows x 64 k
        int idx = i * 128 + t;
        int r = idx >> 3, s = idx & 7;
        size_t g = (size_t)(rowBase + r) * DD + k0 + s * 8;
        uint32_t off = SWZ128((uint32_t)(r * 128 + s * 16));
        CP_ASYNC16(buf + GB_AHI + off, (const char*)(Ahi + g));
        CP_ASYNC16(buf + GB_ALO + off, (const char*)(Alo + g));
    }
#pragma unroll
    for (int i = 0; i < 16; i++) {         // B: 256 rows x 64 k
        int idx = i * 128 + t;
        int r = idx >> 3, s = idx & 7;
        size_t g = (size_t)r * DD + k0 + s * 8;
        uint32_t off = SWZ128((uint32_t)(r * 128 + s * 16));
        CP_ASYNC16(buf + GB_BHI + off, (const char*)(Bhi + g));
        CP_ASYNC16(buf + GB_BLO + off, (const char*)(Blo + g));
    }
}
#endif

__global__ __launch_bounds__(128) void tc_gemm(
    const float* __restrict__ b0, const float* __restrict__ b1, const float* __restrict__ b2,
    float* __restrict__ Y, int in_sel, int mode)  // mode 0 = fused QKV, 1 = O-proj
{
    extern __shared__ char smem[];
    const int t = threadIdx.x;
    const int cb = blockIdx.x;
    const int rowBase = blockIdx.y * 128;

    int w, rowInW;
    if (mode == 0) { w = cb / 3; rowInW = (cb - w * 3) * 256; }
    else           { w = 3;      rowInW = cb * 256; }

    const __nv_bfloat16* Ahi = in_sel ? g_chi : g_xhi;
    const __nv_bfloat16* Alo = in_sel ? g_clo : g_xlo;
    const __nv_bfloat16* Bhi = g_wthi[w] + (size_t)rowInW * DD;
    const __nv_bfloat16* Blo = g_wtlo[w] + (size_t)rowInW * DD;

    const int gRow = rowBase + t;
    const int bb = gRow >> 11, ss = gRow & 2047;

#if HAS_TC
    const uint32_t sbase = smem_u32(smem);
    const int wid = t >> 5;

    if (wid == 0) { TCGEN05_ALLOC(sbase, 256); TCGEN05_RELINQUISH(); }
    if (t == 0) MBARRIER_INIT(sbase + 8, 1);
    __syncthreads();
    uint32_t tmem;
    asm volatile("ld.shared.b32 %0, [%1];" : "=r"(tmem) : "r"(sbase));

    // hoisted descriptors (buffer 0 / buffer 1)
    const uint64_t hAhi0 = MAKE_SMEM_DESC(sbase + 1024 + GB_AHI);
    const uint64_t hAlo0 = MAKE_SMEM_DESC(sbase + 1024 + GB_ALO);
    const uint64_t hBhi0 = MAKE_SMEM_DESC(sbase + 1024 + GB_BHI);
    const uint64_t hBlo0 = MAKE_SMEM_DESC(sbase + 1024 + GB_BLO);
    const uint64_t hAhi1 = MAKE_SMEM_DESC(sbase + 1024 + GB_SIZE + GB_AHI);
    const uint64_t hAlo1 = MAKE_SMEM_DESC(sbase + 1024 + GB_SIZE + GB_ALO);
    const uint64_t hBhi1 = MAKE_SMEM_DESC(sbase + 1024 + GB_SIZE + GB_BHI);
    const uint64_t hBlo1 = MAKE_SMEM_DESC(sbase + 1024 + GB_SIZE + GB_BLO);

    const int nkt = DD / 64;   // 12
    gemm_fill(sbase + 1024, Ahi, Alo, Bhi, Blo, rowBase, 0, t);
    CP_COMMIT();

    for (int kt = 0; kt < nkt; kt++) {
        if (kt > 0) MBARRIER_WAIT_PARITY(sbase + 8, (kt - 1) & 1);
        if (kt + 1 < nkt) {
            gemm_fill(sbase + 1024 + ((kt + 1) & 1) * GB_SIZE, Ahi, Alo, Bhi, Blo,
                      rowBase, (kt + 1) * 64, t);
            CP_COMMIT();
            CP_WAIT(1);
        } else {
            CP_WAIT(0);
        }
        FENCE_PROXY_ASYNC();
        __syncthreads();

        if (wid == 0) {
            if (elect_one_pred()) {
                const bool b1sel = (kt & 1) != 0;
                const uint64_t dAhi = b1sel ? hAhi1 : hAhi0;
                const uint64_t dAlo = b1sel ? hAlo1 : hAlo0;
                const uint64_t dBhi = b1sel ? hBhi1 : hBhi0;
                const uint64_t dBlo = b1sel ? hBlo1 : hBlo0;
#pragma unroll
                for (int ks = 0; ks < 4; ks++) {
#pragma unroll
                    for (int nh = 0; nh < 2; nh++) {
                        const uint64_t ao = ks * 2;
                        const uint64_t bo = nh * 1024 + ks * 2;
                        const bool first = (kt == 0) && (ks == 0);
                        mma_f16_ss(tmem + nh * 128, dAhi + ao, dBhi + bo, GEMM_IDESC, !first);
                        mma_f16_ss(tmem + nh * 128, dAhi + ao, dBlo + bo, GEMM_IDESC, true);
                        mma_f16_ss(tmem + nh * 128, dAlo + ao, dBhi + bo, GEMM_IDESC, true);
                    }
                }
                TCGEN05_COMMIT(sbase + 8);
            }
        }
    }
    MBARRIER_WAIT_PARITY(sbase + 8, (nkt - 1) & 1);
    TCGEN05_FENCE_AFTER();

    float* Ds = reinterpret_cast<float*>(smem + 1024);
#pragma unroll 1
    for (int qr = 0; qr < 4; qr++) {
        uint32_t d0[32], d1[32];
        TCGEN05_LD_32X32B_X32(d0, tmem + qr * 64);
        TCGEN05_LD_32X32B_X32(d1, tmem + qr * 64 + 32);
        TCGEN05_WAIT_LD();
        __syncthreads();
#pragma unroll
        for (int j = 0; j < 32; j++) Ds[t * 65 + j] = __uint_as_float(d0[j]);
#pragma unroll
        for (int j = 0; j < 32; j++) Ds[t * 65 + 32 + j] = __uint_as_float(d1[j]);
        __syncthreads();

        const int cw = rowInW + qr * 64;
        int out_sel; const float* bias;
        if (mode == 0) { out_sel = w; bias = (w == 0) ? b0 : (w == 1) ? b1 : b2; }
        else           { out_sel = 3; bias = b0; }

        if (out_sel == 2) {
            const int hdl = t >> 1, sh = t & 1;
            const float bv = __ldg(&bias[cw + hdl]);
            const int hh = cw >> 6;
            const size_t dstoff = ((size_t)(bb * HH + hh) * HDD + hdl) * SS
                                  + (rowBase & 2047) + sh * 64;
#pragma unroll
            for (int c = 0; c < 4; c++) {
                uint32_t hp[8], lp[8];
#pragma unroll
                for (int e = 0; e < 8; e++) {
                    float v0 = Ds[(sh * 64 + c * 16 + e * 2 + 0) * 65 + hdl] + bv;
                    float v1 = Ds[(sh * 64 + c * 16 + e * 2 + 1) * 65 + hdl] + bv;
                    float h0 = __bfloat162float(__float2bfloat16(v0));
                    float h1 = __bfloat162float(__float2bfloat16(v1));
                    hp[e] = pack_bf16x2(h0, h1);
                    lp[e] = pack_bf16x2(v0 - h0, v1 - h1);
                }
                *reinterpret_cast<uint4*>(g_vthi + dstoff + c * 16)     = *reinterpret_cast<uint4*>(hp);
                *reinterpret_cast<uint4*>(g_vthi + dstoff + c * 16 + 8) = *reinterpret_cast<uint4*>(hp + 4);
                *reinterpret_cast<uint4*>(g_vtlo + dstoff + c * 16)     = *reinterpret_cast<uint4*>(lp);
                *reinterpret_cast<uint4*>(g_vtlo + dstoff + c * 16 + 8) = *reinterpret_cast<uint4*>(lp + 4);
            }
        } else {
            float vals[64];
#pragma unroll
            for (int j = 0; j < 64; j++) vals[j] = Ds[t * 65 + j];
            epi_store(out_sel, cw >> 6, bb, ss, gRow, cw, vals, bias, Y);
        }
    }

    __syncthreads();
    if (t == 0) MBARRIER_INVAL(sbase + 8);
    __syncthreads();
    if (wid == 0) TCGEN05_DEALLOC(tmem, 256);

#else  // FFMA fallback (non-'a' targets; never runs on GB300)
    float* As = reinterpret_cast<float*>(smem + 1024);
    float* Bs = As + 128 * 33;

#pragma unroll 1
    for (int qr = 0; qr < 4; qr++) {
        float acc[64];
#pragma unroll
        for (int j = 0; j < 64; j++) acc[j] = 0.0f;

        for (int kt = 0; kt < DD / 32; kt++) {
            const int k0 = kt * 32;
            __syncthreads();
#pragma unroll
            for (int k = 0; k < 32; k++) {
                size_t gi = (size_t)(rowBase + t) * DD + k0 + k;
                As[t * 33 + k] = __bfloat162float(Ahi[gi]) + __bfloat162float(Alo[gi]);
            }
#pragma unroll
            for (int i = 0; i < 16; i++) {
                int idx = t * 16 + i;
                int k = idx >> 6, j = idx & 63;
                size_t gi = (size_t)(rowInW + qr * 64 + j) * DD + k0 + k;
                Bs[k * 64 + j] = __bfloat162float(g_wthi[w][gi]) + __bfloat162float(g_wtlo[w][gi]);
            }
            __syncthreads();
#pragma unroll
            for (int k = 0; k < 32; k++) {
                float a = As[t * 33 + k];
#pragma unroll
                for (int j = 0; j < 64; j++) acc[j] += a * Bs[k * 64 + j];
            }
        }
        const int cw = rowInW + qr * 64;
        int out_sel; const float* bias;
        if (mode == 0) { out_sel = w; bias = (w == 0) ? b0 : (w == 1) ? b1 : b2; }
        else           { out_sel = 3; bias = b0; }
        epi_store(out_sel, cw >> 6, bb, ss, gRow, cw, acc, bias, Y);
        __syncthreads();
    }
#endif
}

// ------- tensor-core causal attention, SELECTIVE split-K ----------------
// (R14 structure; issuer-warp descriptors hoisted out of the loop)
#define AT_QHI  1024
#define AT_QLO  (1024 + 16384)
#define AT_K0   (1024 + 32768)   // K buf b at +b*16384 (hi +0, lo +8192)
#define AT_V0   (1024 + 65536)   // V buf b at +b*16384 (hi +0, lo +8192)
#define AT_TOTAL (1024 + 98304)  // 99328 -> 2 CTAs/SM

__global__ __launch_bounds__(288, 2) void tc_attn()
{
    extern __shared__ char smem[];
    const int t = threadIdx.x;
    const int qt = gridDim.x - 1 - blockIdx.x;   // longest CTAs first
    const int h = blockIdx.y;
    const int b = blockIdx.z >> 1, sp = blockIdx.z & 1;
    const bool split = (qt >= SPLIT_QT);
    if (!split && sp == 1) return;               // empty CTA
    const size_t bh = (size_t)(b * HH + h);

    const int n = split ? (qt + 1) : (2 * qt + 2);
    const int ktBeg = split ? sp * n : 0;

#if HAS_TC
    const uint32_t sbase = smem_u32(smem);
    const int wid = t >> 5;          // 0..8
    const int lid = t & 31;
    const bool smx = (wid < 8);
    const int sub = wid & 3;
    const int ch  = wid >> 2;
    const int row = sub * 32 + lid;
    const int qi = qt * 128 + row;
    const uint32_t mbarS0 = sbase + 8;
    const uint32_t mbarS1 = sbase + 16;
    const uint32_t mbarP  = sbase + 24;
    const uint32_t warp_off = ((uint32_t)sub) << 21;

    if (wid == 0) { TCGEN05_ALLOC(sbase, 256); TCGEN05_RELINQUISH(); }
    if (t == 0) { MBARRIER_INIT(mbarS0, 1); MBARRIER_INIT(mbarS1, 1); MBARRIER_INIT(mbarP, 1); }
    __syncthreads();
    uint32_t tmem;
    asm volatile("ld.shared.b32 %0, [%1];" : "=r"(tmem) : "r"(sbase));
    const uint32_t tS0 = tmem;
    const uint32_t tS1 = tmem + 64;
    const uint32_t tO  = tmem + 128;
    const uint32_t tPH = tmem + 192;
    const uint32_t tPL = tmem + 224;

    // ---- prologue: Q tile + K/V(ktBeg) ----
    if (smx) {
        const uint4* qh = reinterpret_cast<const uint4*>(g_qhi + (bh * SS + (size_t)qt * 128) * HDD);
        const uint4* ql = reinterpret_cast<const uint4*>(g_qlo + (bh * SS + (size_t)qt * 128) * HDD);
#pragma unroll
        for (int i = 0; i < 4; i++) {
            int idx = i * 256 + t;
            int r = idx >> 3, slot = idx & 7;
            uint32_t off = SWZ128((uint32_t)(r * 128 + slot * 16));
            *reinterpret_cast<uint4*>(smem + AT_QHI + off) = qh[idx];
            *reinterpret_cast<uint4*>(smem + AT_QLO + off) = ql[idx];
        }
        const int kb0 = ktBeg * 64;
        const uint4* kh = reinterpret_cast<const uint4*>(g_khi + (bh * SS + kb0) * HDD);
        const uint4* kl = reinterpret_cast<const uint4*>(g_klo + (bh * SS + kb0) * HDD);
#pragma unroll
        for (int i = 0; i < 2; i++) {
            int idx = i * 256 + t;
            int r = idx >> 3, slot = idx & 7;
            uint32_t off = SWZ128((uint32_t)(r * 128 + slot * 16));
            *reinterpret_cast<uint4*>(smem + AT_K0 + off) = kh[idx];
            *reinterpret_cast<uint4*>(smem + AT_K0 + 8192 + off) = kl[idx];
            *reinterpret_cast<uint4*>(smem + AT_V0 + off) =
                reinterpret_cast<const uint4*>(g_vthi + (bh * HDD + r) * SS + kb0)[slot];
            *reinterpret_cast<uint4*>(smem + AT_V0 + 8192 + off) =
                reinterpret_cast<const uint4*>(g_vtlo + (bh * HDD + r) * SS + kb0)[slot];
        }
        FENCE_PROXY_ASYNC();
    }
    __syncthreads();

    const uint64_t dQhi = MAKE_SMEM_DESC(sbase + AT_QHI);
    const uint64_t dQlo = MAKE_SMEM_DESC(sbase + AT_QLO);
    // hoisted K/V descriptors (buffer 0 / buffer 1)
    const uint64_t dKhi0 = MAKE_SMEM_DESC(sbase + AT_K0);
    const uint64_t dKlo0 = MAKE_SMEM_DESC(sbase + AT_K0 + 8192);
    const uint64_t dKhi1 = MAKE_SMEM_DESC(sbase + AT_K0 + 16384);
    const uint64_t dKlo1 = MAKE_SMEM_DESC(sbase + AT_K0 + 16384 + 8192);
    const uint64_t dVhi0 = MAKE_SMEM_DESC(sbase + AT_V0);
    const uint64_t dVlo0 = MAKE_SMEM_DESC(sbase + AT_V0 + 8192);
    const uint64_t dVhi1 = MAKE_SMEM_DESC(sbase + AT_V0 + 16384);
    const uint64_t dVlo1 = MAKE_SMEM_DESC(sbase + AT_V0 + 16384 + 8192);

    // prologue: issue S(i=0) -> tS0
    if (wid == 8) {
        if (elect_one_pred()) {
#pragma unroll
            for (int ks = 0; ks < 4; ks++) {
                const uint64_t off = ks * 2;
                mma_f16_ss(tS0, dQhi + off, dKhi0 + off, ATT_IDESC, ks != 0);
                mma_f16_ss(tS0, dQhi + off, dKlo0 + off, ATT_IDESC, true);
                mma_f16_ss(tS0, dQlo + off, dKhi0 + off, ATT_IDESC, true);
            }
            TCGEN05_COMMIT(mbarS0);
        }
    }

    float lpart = 0.0f;
    int phP = 0;

    for (int i = 0; i < n; i++) {
        const int kt = ktBeg + i;
        const bool pre = (i + 1 < n);
        uint4 pvh[2], pvl[2];

        // --- load warps: store K(i+1), prefetch V(i+1) ---
        if (smx && pre) {
            const int nb = (kt + 1) * 64;
            const uint32_t kb = AT_K0 + ((i + 1) & 1) * 16384;
            const uint4* kh = reinterpret_cast<const uint4*>(g_khi + (bh * SS + nb) * HDD);
            const uint4* kl = reinterpret_cast<const uint4*>(g_klo + (bh * SS + nb) * HDD);
#pragma unroll
            for (int j = 0; j < 2; j++) {
                int idx = j * 256 + t;
                int r = idx >> 3, slot = idx & 7;
                uint32_t off = SWZ128((uint32_t)(r * 128 + slot * 16));
                *reinterpret_cast<uint4*>(smem + kb + off) = kh[idx];
                *reinterpret_cast<uint4*>(smem + kb + 8192 + off) = kl[idx];
                pvh[j] = reinterpret_cast<const uint4*>(g_vthi + (bh * HDD + r) * SS + nb)[slot];
                pvl[j] = reinterpret_cast<const uint4*>(g_vtlo + (bh * HDD + r) * SS + nb)[slot];
            }
            FENCE_PROXY_ASYNC();
        }
        __syncthreads();   // the ONLY sync per iteration

        if (wid == 8) {
            // ---- issuer warp: PV(i-1) first, then S(i+1) ----
            if (elect_one_pred()) {
                TCGEN05_FENCE_AFTER();
                if (i > 0) {
                    const bool vb1 = ((i - 1) & 1) != 0;
                    const uint64_t dVhi = vb1 ? dVhi1 : dVhi0;
                    const uint64_t dVlo = vb1 ? dVlo1 : dVlo0;
#pragma unroll
                    for (int ks = 0; ks < 4; ks++) {
                        const uint64_t off = ks * 2;
                        const bool first = (i == 1) && (ks == 0);
                        mma_f16_ts(tO, tPH + ks * 8, dVhi + off, ATT_IDESC, !first);
                        mma_f16_ts(tO, tPH + ks * 8, dVlo + off, ATT_IDESC, true);
                        mma_f16_ts(tO, tPL + ks * 8, dVhi + off, ATT_IDESC, true);
                    }
                    TCGEN05_COMMIT(mbarP);
                }
                if (pre) {
                    const bool kb1 = ((i + 1) & 1) != 0;
                    const uint64_t dKhi = kb1 ? dKhi1 : dKhi0;
                    const uint64_t dKlo = kb1 ? dKlo1 : dKlo0;
                    const uint32_t tSn = kb1 ? tS1 : tS0;
#pragma unroll
                    for (int ks = 0; ks < 4; ks++) {
                        const uint64_t off = ks * 2;
                        mma_f16_ss(tSn, dQhi + off, dKhi + off, ATT_IDESC, ks != 0);
                        mma_f16_ss(tSn, dQhi + off, dKlo + off, ATT_IDESC, true);
                        mma_f16_ss(tSn, dQlo + off, dKhi + off, ATT_IDESC, true);
                    }
                    TCGEN05_COMMIT(kb1 ? mbarS1 : mbarS0);
                }
            }
        } else {
            // ---- softmax warps ----
            MBARRIER_WAIT_PARITY((i & 1) ? mbarS1 : mbarS0, (i >> 1) & 1);
            TCGEN05_FENCE_AFTER();

            float s_[32];
            {
                const uint32_t tSc = ((i & 1) ? tS1 : tS0) + ch * 32;
                TCGEN05_LD_32X32B_X32(reinterpret_cast<uint32_t*>(s_), tSc);
            }
            TCGEN05_WAIT_LD();

            const int cb0 = kt * 64 + ch * 32;
            if (kt >= 2 * qt) {
#pragma unroll
                for (int j = 0; j < 32; j++)
                    if (cb0 + j > qi) s_[j] = -1e30f;
            }
            float sum = 0.0f;
#pragma unroll
            for (int j = 0; j < 32; j++) {
                float e = (j % 3 == 0) ? exp2_poly(s_[j]) : ex2_mufu(s_[j]);
                s_[j] = e;
                sum += e;
            }
            lpart += sum;

            if (i > 0) { MBARRIER_WAIT_PARITY(mbarP, phP & 1); phP++; }

            // split P -> bf16 hi/lo straight into TMEM
            {
                uint32_t hw[16], lw[16];
#pragma unroll
                for (int g = 0; g < 16; g++) {
                    float p0 = s_[g*2+0], p1 = s_[g*2+1];
                    float h0 = __bfloat162float(__float2bfloat16(p0));
                    float h1 = __bfloat162float(__float2bfloat16(p1));
                    hw[g] = pack_bf16x2(h0, h1);
                    lw[g] = pack_bf16x2(p0 - h0, p1 - h1);
                }
                TCGEN05_ST_32X32B_X16(tPH + ch * 16 + warp_off, hw);
                TCGEN05_ST_32X32B_X16(tPL + ch * 16 + warp_off, lw);
                TCGEN05_WAIT_ST();
            }
            TCGEN05_FENCE_BEFORE();

            // store V(i+1) (buffer free: PV(i-1) waited above)
            if (pre) {
                const uint32_t vb = AT_V0 + ((i + 1) & 1) * 16384;
#pragma unroll
                for (int j = 0; j < 2; j++) {
                    int idx = j * 256 + t;
                    int r = idx >> 3, slot = idx & 7;
                    uint32_t off = SWZ128((uint32_t)(r * 128 + slot * 16));
                    *reinterpret_cast<uint4*>(smem + vb + off) = pvh[j];
                    *reinterpret_cast<uint4*>(smem + vb + 8192 + off) = pvl[j];
                }
                FENCE_PROXY_ASYNC();
            }
        }
    }

    // ---- tail: issue final PV(n-1) ----
    __syncthreads();
    if (wid == 8) {
        if (elect_one_pred()) {
            TCGEN05_FENCE_AFTER();
            const bool vb1 = ((n - 1) & 1) != 0;
            const uint64_t dVhi = vb1 ? dVhi1 : dVhi0;
            const uint64_t dVlo = vb1 ? dVlo1 : dVlo0;
#pragma unroll
            for (int ks = 0; ks < 4; ks++) {
                const uint64_t off = ks * 2;
                const bool first = (n == 1) && (ks == 0);
                mma_f16_ts(tO, tPH + ks * 8, dVhi + off, ATT_IDESC, !first);
                mma_f16_ts(tO, tPH + ks * 8, dVlo + off, ATT_IDESC, true);
                mma_f16_ts(tO, tPL + ks * 8, dVhi + off, ATT_IDESC, true);
            }
            TCGEN05_COMMIT(mbarP);
        }
    }

    MBARRIER_WAIT_PARITY(mbarP, (n - 1) & 1);
    TCGEN05_FENCE_AFTER();

    // ---- epilogue ----
    if (smx) {
        float* sums = reinterpret_cast<float*>(smem + AT_QHI);
        sums[ch * 128 + row] = lpart;
    }
    __syncthreads();

    if (smx) {
        float O[32];
        TCGEN05_LD_32X32B_X32(reinterpret_cast<uint32_t*>(O), tO + ch * 32);
        TCGEN05_WAIT_LD();

        const float* sums = reinterpret_cast<const float*>(smem + AT_QHI);
        const float ltot = sums[row] + sums[128 + row];

        if (split) {
            const size_t prow = bh * SS + qi;
            if (ch == 0) g_lp[sp][prow] = ltot;
            float* dst = g_po + ((size_t)sp * NROWS_ATT + prow) * HDD + ch * 32;
#pragma unroll
            for (int g = 0; g < 8; g++)
                *reinterpret_cast<float4*>(dst + g * 4) = *reinterpret_cast<float4*>(O + g * 4);
        } else {
            const float inv = 1.0f / ltot;
            size_t ob = ((size_t)b * SS + qi) * DD + h * HDD + ch * 32;
#pragma unroll
            for (int g = 0; g < 4; g++) {
                uint32_t hw[4], lw[4];
#pragma unroll
                for (int e2 = 0; e2 < 4; e2++) {
                    float v0 = O[g*8 + e2*2+0] * inv;
                    float v1 = O[g*8 + e2*2+1] * inv;
                    float h0 = __bfloat162float(__float2bfloat16(v0));
                    float h1 = __bfloat162float(__float2bfloat16(v1));
                    hw[e2] = pack_bf16x2(h0, h1);
                    lw[e2] = pack_bf16x2(v0 - h0, v1 - h1);
                }
                *reinterpret_cast<uint4*>(g_chi + ob + g*8) = *reinterpret_cast<uint4*>(hw);
                *reinterpret_cast<uint4*>(g_clo + ob + g*8) = *reinterpret_cast<uint4*>(lw);
            }
        }
    }

    // ---- last-finisher combine (split rows only) ----
    if (split) {
        __threadfence();
        __syncthreads();
        int* sflag = reinterpret_cast<int*>(smem + 32);
        if (t == 0) {
            const int fidx = (int)bh * (16 - SPLIT_QT) + (qt - SPLIT_QT);
            *sflag = atomicAdd(&g_flag[fidx], 1);
        }
        __syncthreads();
        if (*sflag == 1 && smx) {
            const size_t prow = bh * SS + qi;
            const float inv = 1.0f / (g_lp[0][prow] + g_lp[1][prow]);
            const float4* p0 = reinterpret_cast<const float4*>(g_po + prow * HDD + ch * 32);
            const float4* p1 = reinterpret_cast<const float4*>(
                g_po + ((size_t)NROWS_ATT + prow) * HDD + ch * 32);
            size_t ob = ((size_t)b * SS + qi) * DD + h * HDD + ch * 32;
#pragma unroll
            for (int g = 0; g < 4; g++) {
                float4 a0 = p0[g*2+0], a1 = p0[g*2+1];
                float4 c0 = p1[g*2+0], c1 = p1[g*2+1];
                float v[8];
                v[0] = (a0.x + c0.x) * inv; v[1] = (a0.y + c0.y) * inv;
                v[2] = (a0.z + c0.z) * inv; v[3] = (a0.w + c0.w) * inv;
                v[4] = (a1.x + c1.x) * inv; v[5] = (a1.y + c1.y) * inv;
                v[6] = (a1.z + c1.z) * inv; v[7] = (a1.w + c1.w) * inv;
                uint32_t hw[4], lw[4];
#pragma unroll
                for (int e = 0; e < 4; e++) {
                    float h0 = __bfloat162float(__float2bfloat16(v[e*2+0]));
                    float h1 = __bfloat162float(__float2bfloat16(v[e*2+1]));
                    hw[e] = pack_bf16x2(h0, h1);
                    lw[e] = pack_bf16x2(v[e*2+0] - h0, v[e*2+1] - h1);
                }
                *reinterpret_cast<uint4*>(g_chi + ob + g*8) = *reinterpret_cast<uint4*>(hw);
                *reinterpret_cast<uint4*>(g_clo + ob + g*8) = *reinterpret_cast<uint4*>(lw);
            }
        }
    }

    __syncthreads();
    if (t == 0) { MBARRIER_INVAL(mbarS0); MBARRIER_INVAL(mbarS1); MBARRIER_INVAL(mbarP); }
    __syncthreads();
    if (wid == 0) TCGEN05_DEALLOC(tmem, 256);

#else  // scalar fallback (never runs on GB300)
    __shared__ int sflag2;
    if (t < 128) {
        const int qi2 = qt * 128 + t;
        float q[64];
#pragma unroll
        for (int d = 0; d < 64; d++) {
            size_t o = (bh * SS + qi2) * HDD + d;
            q[d] = __bfloat162float(g_qhi[o]) + __bfloat162float(g_qlo[o]);
        }
        float O[64];
#pragma unroll
        for (int d = 0; d < 64; d++) O[d] = 0.0f;
        float l = 0.0f;
        const int kLo = ktBeg * 64;
        const int kHi = (ktBeg + n) * 64 - 1;
        const int kEnd = (qi2 < kHi) ? qi2 : kHi;
        for (int k = kLo; k <= kEnd; k++) {
            float s = 0.0f;
            size_t kb = (bh * SS + k) * HDD;
            for (int d = 0; d < 64; d++)
                s += q[d] * (__bfloat162float(g_khi[kb + d]) + __bfloat162float(g_klo[kb + d]));
            float p = exp2f(s);
            l += p;
            for (int d = 0; d < 64; d++) {
                size_t vo = (bh * HDD + d) * SS + k;
                O[d] += p * (__bfloat162float(g_vthi[vo]) + __bfloat162float(g_vtlo[vo]));
            }
        }
        if (split) {
            const size_t prow = bh * SS + qi2;
            g_lp[sp][prow] = l;
            float* dst = g_po + ((size_t)sp * NROWS_ATT + prow) * HDD;
            for (int d = 0; d < 64; d++) dst[d] = O[d];
        } else {
            const float inv = 1.0f / l;
            size_t ob = ((size_t)b * SS + qi2) * DD + h * HDD;
            for (int d = 0; d < 64; d++) {
                float v = O[d] * inv;
                __nv_bfloat16 hb = __float2bfloat16(v);
                g_chi[ob + d] = hb;
                g_clo[ob + d] = __float2bfloat16(v - __bfloat162float(hb));
            }
        }
    }
    if (split) {
        __threadfence();
        __syncthreads();
        if (t == 0) {
            const int fidx = (int)bh * (16 - SPLIT_QT) + (qt - SPLIT_QT);
            sflag2 = atomicAdd(&g_flag[fidx], 1);
        }
        __syncthreads();
        if (sflag2 == 1 && t < 128) {
            const int qi2 = qt * 128 + t;
            const size_t prow = bh * SS + qi2;
            const float inv = 1.0f / (g_lp[0][prow] + g_lp[1][prow]);
            size_t ob = ((size_t)b * SS + qi2) * DD + h * HDD;
            for (int d = 0; d < 64; d++) {
                float v = (g_po[prow * HDD + d] + g_po[(size_t)NROWS_ATT * HDD + prow * HDD + d]) * inv;
                __nv_bfloat16 hb = __float2bfloat16(v);
                g_chi[ob + d] = hb;
                g_clo[ob + d] = __float2bfloat16(v - __bfloat162float(hb));
            }
        }
    }
#endif
}

// ---------------------------------------------------------------------------
extern "C" void kernel_launch(void* const* d_in, const int* in_sizes, int n_in,
                              void* d_out, int out_size)
{
    const float* x  = (const float*)d_in[0];
    const float* wq = (const float*)d_in[1];
    const float* bq = (const float*)d_in[2];
    const float* wk = (const float*)d_in[3];
    const float* bk = (const float*)d_in[4];
    const float* wv = (const float*)d_in[5];
    const float* bv = (const float*)d_in[6];
    const float* wo = (const float*)d_in[7];
    const float* bo = (const float*)d_in[8];
    float* out = (float*)d_out;

    cudaFuncSetAttribute(tc_gemm, cudaFuncAttributeMaxDynamicSharedMemorySize, GM_TOTAL);
    cudaFuncSetAttribute(tc_attn, cudaFuncAttributeMaxDynamicSharedMemorySize, AT_TOTAL);

    // fused prep: weight transpose+split (2304 blocks) + x split (6144 blocks)
    prep_kernel<<<8448, 256>>>(x, wq, wk, wv, wo);

    // fused QKV: N = 2304 -> 9 col-blocks of 256
    tc_gemm<<<dim3(9, MROWS / 128), 128, GM_TOTAL>>>(bq, bk, bv, nullptr, 0, 0);

    // selective split-K attention with in-kernel last-finisher combine
    tc_attn<<<dim3(SS / 128, HH, BB * 2), 288, AT_TOTAL>>>();

    // O-projection: N = 768 -> 3 col-blocks of 256
    tc_gemm<<<dim3(3, MROWS / 128), 128, GM_TOTAL>>>(bo, bo, bo, out, 1, 1);
}